// round 14
// baseline (speedup 1.0000x reference)
#include <cuda_runtime.h>
#include <cuda_fp16.h>
#include <math.h>
#include <stdint.h>

#define Bz 32
#define Ss 96
#define Tt 96
#define Ee 200
#define Hh 512
#define Vv 30000
#define G4 2048
#define VPAD 30208   // 118 * 256
#define MPAD 3072    // 24 * 128
#define XM 3072
#define XN 2048
#define XK 200
#define NKS 13       // ceil(200/16)

typedef unsigned long long ull;

// Pair layout for (k,b) arrays: element (k,b) at [(k*16+(b&15))*2 + (b>>4)]
__device__ float d_gxf[(size_t)Ss * G4 * Bz];
__device__ float d_gxb[(size_t)Ss * G4 * Bz];
__device__ float d_gxd[(size_t)(Tt - 1) * G4 * Bz];
__device__ float d_hping[2 * 2 * Hh * Bz];
__device__ float d_hdping[2 * Hh * Bz];
__device__ float d_hfin[2 * Hh * Bz];
__device__ float d_cfin[2 * Hh * Bz];
__device__ float d_c0[Hh * Bz];
// fp16 fragment buffers
__device__ uint4 d_ahf[(size_t)MPAD * Hh / 8];   // decoder h, m16n8k16 A-frag
__device__ uint4 d_whf[(size_t)VPAD * Hh / 8];   // fc_W, m16n8k16 B-frag
// x-gemm fp16 hi/lo fragment buffers
__device__ uint4 d_x16ah[3][48 * 4 * NKS * 32];
__device__ uint4 d_x16al[3][48 * 4 * NKS * 32];
__device__ uint4 d_x16bh[3][64 * NKS * 2 * 32];
__device__ uint4 d_x16bl[3][64 * NKS * 2 * 32];
__device__ int d_idxf[Ss * Bz];
__device__ int d_idxb[Ss * Bz];
__device__ int d_idxd[(Tt - 1) * Bz];
__device__ ull d_lf_enc[8 * 16];
__device__ ull d_rt_enc2[32];
__device__ ull d_lf_dec[8 * 16];
__device__ ull d_rt_dec;

__device__ __forceinline__ ull pack2(float x, float y) {
    ull r; asm("mov.b64 %0,{%1,%2};" : "=l"(r) : "f"(x), "f"(y)); return r;
}
__device__ __forceinline__ ull ffma2(ull a, ull b, ull c) {
    ull d; asm("fma.rn.f32x2 %0,%1,%2,%3;" : "=l"(d) : "l"(a), "l"(b), "l"(c)); return d;
}
__device__ __forceinline__ ull fadd2(ull a, ull b) {
    ull d; asm("add.rn.f32x2 %0,%1,%2;" : "=l"(d) : "l"(a), "l"(b)); return d;
}

__device__ __forceinline__ void grid_sync2(ull* leaf, ull* root, int lbid, int nleaf) {
    __syncthreads();
    if (threadIdx.x == 0) {
        __threadfence();
        ull a = atomicAdd(&leaf[(lbid >> 4) * 16], 1ULL) + 1ULL;
        ull phase = (a - 1ULL) >> 4;
        if ((a & 15ULL) == 0ULL) atomicAdd(root, 1ULL);
        ull target = (phase + 1ULL) * (ull)nleaf;
        while (*((volatile ull*)root) < target) { }
        __threadfence();
    }
    __syncthreads();
}

__device__ __forceinline__ void split_h2(float x0, float x1, unsigned& hi, unsigned& lo) {
    __half h0 = __float2half_rn(x0), h1 = __float2half_rn(x1);
    __half l0 = __float2half_rn(x0 - __half2float(h0));
    __half l1 = __float2half_rn(x1 - __half2float(h1));
    __half2 hh = __halves2half2(h0, h1), ll = __halves2half2(l0, l1);
    hi = *(unsigned*)&hh; lo = *(unsigned*)&ll;
}

// launch 0: indices + d_ahf pad-chunk zero
__global__ void k_idx(const int* __restrict__ Problem, const int* __restrict__ LF) {
    int m = blockIdx.x * blockDim.x + threadIdx.x;
    if (m < Ss * Bz) {
        int s = m >> 5, b = m & 31;
        d_idxf[m] = Problem[b * Ss + s];
        d_idxb[m] = Problem[b * Ss + (Ss - 1 - s)];
    }
    if (m < (Tt - 1) * Bz) {
        int t = m >> 5, b = m & 31;
        d_idxd[m] = LF[b * Tt + t];
    }
    uint4* p = d_ahf + (size_t)47 * 4096;
    uint4 z = make_uint4(0u, 0u, 0u, 0u);
    for (int i = m; i < 4096; i += 12 * 256) p[i] = z;
}

__global__ void k_zero_t0(float* __restrict__ out) {
    long i = (long)blockIdx.x * blockDim.x + threadIdx.x;
    if (i < (long)Bz * Vv) {
        long b = i / Vv;
        long n = i - b * Vv;
        out[b * (long)Tt * Vv + n] = 0.f;
    }
}

// ---- permW v2: smem-tiled, coalesced. grid (472, 8) -----------------------
__global__ void __launch_bounds__(256) k_permW(const float* __restrict__ W) {
    __shared__ float sw[64][65];
    int tid = threadIdx.x;
    int n0 = blockIdx.x * 64;
    int k0 = blockIdx.y * 64;
    for (int i = tid; i < 1024; i += 256) {
        int row = i >> 4, f4 = i & 15;
        float4 v = make_float4(0.f, 0.f, 0.f, 0.f);
        if (n0 + row < Vv)
            v = *(const float4*)(W + (size_t)(n0 + row) * Hh + k0 + f4 * 4);
        sw[row][f4 * 4 + 0] = v.x; sw[row][f4 * 4 + 1] = v.y;
        sw[row][f4 * 4 + 2] = v.z; sw[row][f4 * 4 + 3] = v.w;
    }
    __syncthreads();
    for (int e = tid; e < 512; e += 256) {
        int lane = e & 31, q = (e >> 5) & 3, ksl = (e >> 7) & 3;
        unsigned comp[4];
#pragma unroll
        for (int c = 0; c < 4; c++) {
            int sub = c >> 1, khi = c & 1;
            int nl = (q * 2 + sub) * 8 + (lane >> 2);
            int kl = ksl * 16 + khi * 8 + (lane & 3) * 2;
            __half2 h2 = __floats2half2_rn(sw[nl][kl], sw[nl][kl + 1]);
            comp[c] = *(unsigned*)&h2;
        }
        int ks_g = blockIdx.y * 4 + ksl;
        d_whf[(size_t)blockIdx.x * 4096 + ks_g * 128 + q * 32 + lane]
            = make_uint4(comp[0], comp[1], comp[2], comp[3]);
    }
}

// ---- gathered embeddings -> fp16 hi/lo A-fragments ------------------------
__global__ void __launch_bounds__(256) k_permX(const float* __restrict__ Eenc,
                                               const float* __restrict__ Edec) {
    int which = blockIdx.z;
    int Mlim = (which == 2) ? 3040 : XM;
    const float* E = (which == 2) ? Edec : Eenc;
    const int* ridx = (which == 0) ? d_idxf : (which == 1) ? d_idxb : d_idxd;
    int o = blockIdx.x * 256 + threadIdx.x;
    int lane = o & 31;
    int t = o >> 5;
    int ks = t % NKS;
    int t2 = t / NKS;
    int mt = t2 & 3, wt = t2 >> 2;
    int kb = ks * 16 + (lane & 3) * 2;
    int mrow = wt * 64 + mt * 16 + (lane >> 2);
    unsigned hic[4], loc[4];
#pragma unroll
    for (int c = 0; c < 4; c++) {
        int hi8 = c & 1, khi = c >> 1;
        int m = mrow + hi8 * 8;
        int k = kb + khi * 8;
        float v0 = 0.f, v1 = 0.f;
        if (m < Mlim && k < XK) {
            const float* r = E + (size_t)ridx[m] * XK;
            v0 = r[k];
            if (k + 1 < XK) v1 = r[k + 1];
        }
        split_h2(v0, v1, hic[c], loc[c]);
    }
    d_x16ah[which][o] = make_uint4(hic[0], hic[1], hic[2], hic[3]);
    d_x16al[which][o] = make_uint4(loc[0], loc[1], loc[2], loc[3]);
}

// ---- Wih -> fp16 hi/lo B-fragments ---------------------------------------
__global__ void __launch_bounds__(256) k_permWih(const float* __restrict__ W0,
                                                 const float* __restrict__ W1,
                                                 const float* __restrict__ W2) {
    int which = blockIdx.z;
    const float* W = (which == 0) ? W0 : (which == 1) ? W1 : W2;
    int o = blockIdx.x * 256 + threadIdx.x;
    int lane = o & 31;
    int q2 = (o >> 5) & 1;
    int t = o >> 6;
    int ks = t % NKS;
    int nt = t / NKS;
    unsigned hic[4], loc[4];
#pragma unroll
    for (int c = 0; c < 4; c++) {
        int sub = c >> 1, khi = c & 1;
        int n = nt * 32 + (q2 * 2 + sub) * 8 + (lane >> 2);
        int k = ks * 16 + khi * 8 + (lane & 3) * 2;
        float v0 = 0.f, v1 = 0.f;
        if (k < XK) {
            v0 = W[(size_t)n * XK + k];
            if (k + 1 < XK) v1 = W[(size_t)n * XK + k + 1];
        }
        split_h2(v0, v1, hic[c], loc[c]);
    }
    d_x16bh[which][o] = make_uint4(hic[0], hic[1], hic[2], hic[3]);
    d_x16bl[which][o] = make_uint4(loc[0], loc[1], loc[2], loc[3]);
}

#define MMA_F16(c0, c1, c2, c3, A0, A1, A2, A3, B0, B1) \
    asm volatile( \
        "mma.sync.aligned.m16n8k16.row.col.f32.f16.f16.f32 " \
        "{%0,%1,%2,%3},{%4,%5,%6,%7},{%8,%9},{%0,%1,%2,%3};" \
        : "+f"(c0), "+f"(c1), "+f"(c2), "+f"(c3) \
        : "r"(A0), "r"(A1), "r"(A2), "r"(A3), "r"(B0), "r"(B1))

// ---- x-gate GEMMs, fp16 hi/lo 3-term ---------------------------------------
__global__ void __launch_bounds__(256) k_xg(const float* __restrict__ bias0,
                                            const float* __restrict__ bias1,
                                            const float* __restrict__ bias2) {
    int which = blockIdx.z;
    const float* bias = (which == 0) ? bias0 : (which == 1) ? bias1 : bias2;
    int Mlim = (which == 2) ? 3040 : XM;
    float* out = (which == 0) ? d_gxf : (which == 1) ? d_gxb : d_gxd;
    int tid = threadIdx.x, w = tid >> 5, lane = tid & 31;
    int wm = w & 1, wn = w >> 1;
    int wt = blockIdx.y * 2 + wm;
    int nt = blockIdx.x * 4 + wn;
    const uint4* Ah = d_x16ah[which] + (size_t)wt * 4 * NKS * 32 + lane;
    const uint4* Al = d_x16al[which] + (size_t)wt * 4 * NKS * 32 + lane;
    const uint4* Bh = d_x16bh[which] + (size_t)nt * NKS * 2 * 32 + lane;
    const uint4* Bl = d_x16bl[which] + (size_t)nt * NKS * 2 * 32 + lane;

    float acc[4][4][4];
#pragma unroll
    for (int a = 0; a < 4; a++)
#pragma unroll
        for (int b = 0; b < 4; b++)
#pragma unroll
            for (int cc = 0; cc < 4; cc++) acc[a][b][cc] = 0.f;

    for (int ks = 0; ks < NKS; ks++) {
        uint4 ah[4], al[4], bh[2], bl[2];
#pragma unroll
        for (int mt = 0; mt < 4; mt++) {
            ah[mt] = Ah[(mt * NKS + ks) * 32];
            al[mt] = Al[(mt * NKS + ks) * 32];
        }
#pragma unroll
        for (int q2 = 0; q2 < 2; q2++) {
            bh[q2] = Bh[(ks * 2 + q2) * 32];
            bl[q2] = Bl[(ks * 2 + q2) * 32];
        }
#pragma unroll
        for (int mt = 0; mt < 4; mt++) {
#pragma unroll
            for (int n8 = 0; n8 < 4; n8++) {
                int q2 = n8 >> 1, sub = n8 & 1;
                unsigned bh0 = sub ? bh[q2].z : bh[q2].x;
                unsigned bh1 = sub ? bh[q2].w : bh[q2].y;
                unsigned bl0 = sub ? bl[q2].z : bl[q2].x;
                unsigned bl1 = sub ? bl[q2].w : bl[q2].y;
                MMA_F16(acc[mt][n8][0], acc[mt][n8][1], acc[mt][n8][2], acc[mt][n8][3],
                        ah[mt].x, ah[mt].y, ah[mt].z, ah[mt].w, bh0, bh1);
                MMA_F16(acc[mt][n8][0], acc[mt][n8][1], acc[mt][n8][2], acc[mt][n8][3],
                        ah[mt].x, ah[mt].y, ah[mt].z, ah[mt].w, bl0, bl1);
                MMA_F16(acc[mt][n8][0], acc[mt][n8][1], acc[mt][n8][2], acc[mt][n8][3],
                        al[mt].x, al[mt].y, al[mt].z, al[mt].w, bh0, bh1);
            }
        }
    }

    int mb = blockIdx.y * 128 + wm * 64;
    int nb = blockIdx.x * 128 + wn * 32;
#pragma unroll
    for (int mt = 0; mt < 4; mt++) {
        int r0 = mb + mt * 16 + (lane >> 2);
#pragma unroll
        for (int n8 = 0; n8 < 4; n8++) {
            int n = nb + n8 * 8 + (lane & 3) * 2;
            float b0 = bias[n], b1 = bias[n + 1];
#pragma unroll
            for (int rh = 0; rh < 2; rh++) {
                int m = r0 + rh * 8;
                if (m < Mlim) {
                    size_t base = ((size_t)(m >> 5) * XN + n) * 32 + (m & 15) * 2 + ((m >> 4) & 1);
                    out[base]      = acc[mt][n8][rh * 2 + 0] + b0;
                    out[base + 32] = acc[mt][n8][rh * 2 + 1] + b1;
                }
            }
        }
    }
}

__device__ __forceinline__ void lstm_cell(float ai, float af, float ag, float ao,
                                          float& c, float& h) {
    float si = 1.f / (1.f + expf(-ai));
    float sf = 1.f / (1.f + expf(-af));
    float so = 1.f / (1.f + expf(-ao));
    float tg = tanhf(ag);
    c = sf * c + si * tg;
    h = so * tanhf(c);
}

#define HS_ROW 9

// =====================================================================
// enc scan: 128 blocks x 512 threads. blocks[0,64)=fwd, [64,128)=bwd.
// 8 j/block; 2 warps per j (w>>1 = jl, w&1 = bhalf -> 8 pairs each).
// =====================================================================
__global__ void __launch_bounds__(512) k_enc_scan(const float* __restrict__ Whf,
                                                  const float* __restrict__ Whb) {
    __shared__ float4 hsh4[256 * HS_ROW];
    __shared__ ull gsh[8][2][4][8];
    int tid = threadIdx.x, w = tid >> 5, lane = tid & 31;
    int g = lane & 3, kc = lane >> 2;
    int jl = w >> 1, bhalf = w & 1;
    int dir = blockIdx.x >> 6;
    int j = (blockIdx.x & 63) * 8 + jl;
    int pq = lane & 7, chalf = (lane >> 3) & 1;
    int bp = bhalf * 8 + pq;
    bool cell_lane = (lane < 16);

    const float* gx = dir ? d_gxb : d_gxf;
    const float* Whh = dir ? Whb : Whf;
    float* hbuf = d_hping + (size_t)dir * (2 * Hh * Bz);
    ull* lf = d_lf_enc + dir * 64;
    ull* rt = &d_rt_enc2[dir * 16];

    float wreg[64];
    {
        const float* wrow = Whh + ((size_t)g * Hh + j) * Hh + kc;
#pragma unroll
        for (int kk = 0; kk < 64; kk++) wreg[kk] = wrow[kk * 8];
    }
    float c = 0.f, h = 0.f;

    for (int s = 0; s < Ss; s++) {
        float ga0 = 0.f, ga1 = 0.f, ga2 = 0.f, ga3 = 0.f;
        if (cell_lane) {
            const float* gxs = gx + (size_t)s * G4 * Bz;
            ga0 = gxs[(0 * Hh + j) * Bz + bp * 2 + chalf];
            ga1 = gxs[(1 * Hh + j) * Bz + bp * 2 + chalf];
            ga2 = gxs[(2 * Hh + j) * Bz + bp * 2 + chalf];
            ga3 = gxs[(3 * Hh + j) * Bz + bp * 2 + chalf];
        }

        if (s > 0) {
            ull acc[8];
#pragma unroll
            for (int i = 0; i < 8; i++) acc[i] = 0ULL;
            const float4* src = (const float4*)(hbuf + (size_t)(s & 1) * (Hh * Bz));
#pragma unroll
            for (int ch = 0; ch < 2; ch++) {
                for (int ii = tid; ii < 2048; ii += 512)
                    hsh4[(ii >> 3) * HS_ROW + (ii & 7)] = src[ch * 2048 + ii];
                __syncthreads();
                const ulonglong2* hs2 = (const ulonglong2*)hsh4;
#pragma unroll
                for (int kk2 = 0; kk2 < 32; kk2++) {
                    float wv = wreg[ch * 32 + kk2];
                    ull w2 = pack2(wv, wv);
                    const ulonglong2* row = hs2 + (kc + (kk2 << 3)) * HS_ROW + bhalf * 4;
#pragma unroll
                    for (int bq = 0; bq < 4; bq++) {
                        ulonglong2 hv = row[bq];
                        acc[2 * bq]     = ffma2(w2, hv.x, acc[2 * bq]);
                        acc[2 * bq + 1] = ffma2(w2, hv.y, acc[2 * bq + 1]);
                    }
                }
                __syncthreads();
            }
#pragma unroll
            for (int i = 0; i < 8; i++) {
                acc[i] = fadd2(acc[i], __shfl_xor_sync(0xffffffffu, acc[i], 4));
                acc[i] = fadd2(acc[i], __shfl_xor_sync(0xffffffffu, acc[i], 8));
                acc[i] = fadd2(acc[i], __shfl_xor_sync(0xffffffffu, acc[i], 16));
            }
            if (lane < 4) {
#pragma unroll
                for (int i = 0; i < 8; i++) gsh[jl][bhalf][lane][i] = acc[i];
            }
            __syncwarp();
            if (cell_lane) {
                const float* gsf = (const float*)&gsh[jl][bhalf][0][0];
                ga0 += gsf[(0 * 8 + pq) * 2 + chalf];
                ga1 += gsf[(1 * 8 + pq) * 2 + chalf];
                ga2 += gsf[(2 * 8 + pq) * 2 + chalf];
                ga3 += gsf[(3 * 8 + pq) * 2 + chalf];
            }
            __syncwarp();
        }
        if (cell_lane) {
            lstm_cell(ga0, ga1, ga2, ga3, c, h);
            hbuf[(size_t)((s + 1) & 1) * (Hh * Bz) + (j * 16 + bp) * 2 + chalf] = h;
        }
        grid_sync2(lf, rt, blockIdx.x & 63, 4);
    }
    if (cell_lane) {
        d_hfin[(size_t)dir * (Hh * Bz) + (j * 16 + bp) * 2 + chalf] = h;
        d_cfin[(size_t)dir * (Hh * Bz) + (j * 16 + bp) * 2 + chalf] = c;
    }
}

// =====================================================================
// dec scan: 128 blocks x 512 threads. 4 j/block; 4 warps per j
// (w>>2 = jl, w&3 = bq4 -> 4 pairs each).
// =====================================================================
__global__ void __launch_bounds__(512) k_dec_scan(const float* __restrict__ Whh) {
    __shared__ float4 hsh4[256 * HS_ROW];
    __shared__ ull gsh[4][4][4][4];
    int tid = threadIdx.x, w = tid >> 5, lane = tid & 31;
    int g = lane & 3, kc = lane >> 2;
    int jl = w >> 2, bq4 = w & 3;
    int j = blockIdx.x * 4 + jl;
    int pq = lane & 3, chalf = (lane >> 2) & 1;
    int bp = bq4 * 4 + pq;
    bool cell_lane = (lane < 8);

    float wreg[64];
    {
        const float* wrow = Whh + ((size_t)g * Hh + j) * Hh + kc;
#pragma unroll
        for (int kk = 0; kk < 64; kk++) wreg[kk] = wrow[kk * 8];
    }
    float c = cell_lane ? d_c0[(j * 16 + bp) * 2 + chalf] : 0.f;
    float h = 0.f;

    int ks_j = j >> 4;
    int khi_j = (j >> 3) & 1;
    int tig_j = (j & 7) >> 1;
    int kpar_j = j & 1;

    for (int t = 0; t < Tt - 1; t++) {
        float ga0 = 0.f, ga1 = 0.f, ga2 = 0.f, ga3 = 0.f;
        if (cell_lane) {
            const float* gxs = d_gxd + (size_t)t * G4 * Bz;
            ga0 = gxs[(0 * Hh + j) * Bz + bp * 2 + chalf];
            ga1 = gxs[(1 * Hh + j) * Bz + bp * 2 + chalf];
            ga2 = gxs[(2 * Hh + j) * Bz + bp * 2 + chalf];
            ga3 = gxs[(3 * Hh + j) * Bz + bp * 2 + chalf];
        }

        ull acc[4];
#pragma unroll
        for (int i = 0; i < 4; i++) acc[i] = 0ULL;
        const float4* src = (const float4*)(d_hdping + (size_t)(t & 1) * (Hh * Bz));
#pragma unroll
        for (int ch = 0; ch < 2; ch++) {
            for (int ii = tid; ii < 2048; ii += 512)
                hsh4[(ii >> 3) * HS_ROW + (ii & 7)] = src[ch * 2048 + ii];
            __syncthreads();
            const ulonglong2* hs2 = (const ulonglong2*)hsh4;
#pragma unroll
            for (int kk2 = 0; kk2 < 32; kk2++) {
                float wv = wreg[ch * 32 + kk2];
                ull w2 = pack2(wv, wv);
                const ulonglong2* row = hs2 + (kc + (kk2 << 3)) * HS_ROW + bq4 * 2;
#pragma unroll
                for (int bq = 0; bq < 2; bq++) {
                    ulonglong2 hv = row[bq];
                    acc[2 * bq]     = ffma2(w2, hv.x, acc[2 * bq]);
                    acc[2 * bq + 1] = ffma2(w2, hv.y, acc[2 * bq + 1]);
                }
            }
            __syncthreads();
        }
#pragma unroll
        for (int i = 0; i < 4; i++) {
            acc[i] = fadd2(acc[i], __shfl_xor_sync(0xffffffffu, acc[i], 4));
            acc[i] = fadd2(acc[i], __shfl_xor_sync(0xffffffffu, acc[i], 8));
            acc[i] = fadd2(acc[i], __shfl_xor_sync(0xffffffffu, acc[i], 16));
        }
        if (lane < 4) {
#pragma unroll
            for (int i = 0; i < 4; i++) gsh[jl][bq4][lane][i] = acc[i];
        }
        __syncwarp();
        if (cell_lane) {
            const float* gsf = (const float*)&gsh[jl][bq4][0][0];
            ga0 += gsf[(0 * 4 + pq) * 2 + chalf];
            ga1 += gsf[(1 * 4 + pq) * 2 + chalf];
            ga2 += gsf[(2 * 4 + pq) * 2 + chalf];
            ga3 += gsf[(3 * 4 + pq) * 2 + chalf];
            lstm_cell(ga0, ga1, ga2, ga3, c, h);
            d_hdping[(size_t)((t + 1) & 1) * (Hh * Bz) + (j * 16 + bp) * 2 + chalf] = h;
            int mrow = t * 32 + bp + 16 * chalf;
            int chunk = mrow >> 6;
            int mt = (mrow >> 4) & 3;
            int row16 = mrow & 15;
            int ga = row16 & 7, hi8 = row16 >> 3;
            int lane_f = ga * 4 + tig_j;
            int comp = hi8 + 2 * khi_j;
            size_t hidx = (((size_t)chunk * 4096 + ks_j * 128 + mt * 32 + lane_f) * 4
                           + comp) * 2 + kpar_j;
            ((__half*)d_ahf)[hidx] = __float2half_rn(h);
        }
        grid_sync2(d_lf_dec, &d_rt_dec, blockIdx.x, 8);
    }
}

__global__ void __launch_bounds__(256) k_h0c0(const float* __restrict__ Wh,
                                              const float* __restrict__ bh,
                                              const float* __restrict__ Wc,
                                              const float* __restrict__ bc) {
    int gg = blockIdx.x * blockDim.x + threadIdx.x;
    int j = gg >> 5, b = gg & 31;
    int bp = b & 15, hf = b >> 4;
    const float* hfp = d_hfin + bp * 2 + hf;
    const float* cfp = d_cfin + bp * 2 + hf;
    const float* whr = Wh + (size_t)j * (2 * Hh);
    const float* wcr = Wc + (size_t)j * (2 * Hh);
    float ah = bh[j], ac = bc[j];
#pragma unroll 8
    for (int k = 0; k < 2 * Hh; k++) {
        ah += whr[k] * hfp[k * 32];
        ac += wcr[k] * cfp[k * 32];
    }
    d_hdping[(j * 16 + bp) * 2 + hf] = ah;
    d_c0[(j * 16 + bp) * 2 + hf] = ac;
}

// Logits: fp16 m16n8k16. CTA 128m x 256n, 512 threads, warp 64x32.
__global__ void __launch_bounds__(512, 1) k_logits_h(const float* __restrict__ fcb,
                                                     float* __restrict__ out) {
    int tid = threadIdx.x, w = tid >> 5, lane = tid & 31;
    int wm = w & 1, wn = w >> 1;
    int mtile = blockIdx.y, ntile = blockIdx.x;

    const uint4* Ab = d_ahf + (size_t)(mtile * 2 + wm) * 4096 + lane;
    const uint4* Bb = d_whf + (size_t)(ntile * 4 + (wn >> 1)) * 4096
                      + (wn & 1) * 64 + lane;

    float acc[4][4][4];
#pragma unroll
    for (int a = 0; a < 4; a++)
#pragma unroll
        for (int b = 0; b < 4; b++)
#pragma unroll
            for (int cc = 0; cc < 4; cc++) acc[a][b][cc] = 0.f;

    uint4 av[2][4], bv[2][2];
#pragma unroll
    for (int q = 0; q < 4; q++) av[0][q] = Ab[q * 32];
#pragma unroll
    for (int p = 0; p < 2; p++) bv[0][p] = Bb[p * 32];

    for (int ks = 0; ks < 32; ks++) {
        int cur = ks & 1, nxt = cur ^ 1;
        if (ks < 31) {
            const uint4* An = Ab + (ks + 1) * 128;
            const uint4* Bn = Bb + (ks + 1) * 128;
#pragma unroll
            for (int q = 0; q < 4; q++) av[nxt][q] = An[q * 32];
#pragma unroll
            for (int p = 0; p < 2; p++) bv[nxt][p] = Bn[p * 32];
        }
#pragma unroll
        for (int mt = 0; mt < 4; mt++) {
            unsigned a0 = av[cur][mt].x, a1 = av[cur][mt].y;
            unsigned a2 = av[cur][mt].z, a3 = av[cur][mt].w;
#pragma unroll
            for (int p = 0; p < 2; p++) {
                MMA_F16(acc[mt][2 * p][0], acc[mt][2 * p][1],
                        acc[mt][2 * p][2], acc[mt][2 * p][3],
                        a0, a1, a2, a3, bv[cur][p].x, bv[cur][p].y);
                MMA_F16(acc[mt][2 * p + 1][0], acc[mt][2 * p + 1][1],
                        acc[mt][2 * p + 1][2], acc[mt][2 * p + 1][3],
                        a0, a1, a2, a3, bv[cur][p].z, bv[cur][p].w);
            }
        }
    }

    int mb = mtile * 128 + wm * 64;
    int nb = ntile * 256 + wn * 32;
#pragma unroll
    for (int mt = 0; mt < 4; mt++) {
        int r0 = mb + mt * 16 + (lane >> 2);
#pragma unroll
        for (int nt = 0; nt < 4; nt++) {
            int n = nb + nt * 8 + (lane & 3) * 2;
            if (n >= Vv) continue;
            float b0 = fcb[n];
            float b1 = fcb[n + 1];
#pragma unroll
            for (int rh = 0; rh < 2; rh++) {
                int m = r0 + rh * 8;
                if (m < 3040) {
                    int b = m & 31, ts = m >> 5;
                    size_t o = ((size_t)b * Tt + ts + 1) * (size_t)Vv + n;
                    out[o]     = acc[mt][nt][rh * 2 + 0] + b0;
                    out[o + 1] = acc[mt][nt][rh * 2 + 1] + b1;
                }
            }
        }
    }
}

extern "C" void kernel_launch(void* const* d_in, const int* in_sizes, int n_in,
                              void* d_out, int out_size) {
    (void)in_sizes; (void)n_in; (void)out_size;
    const int*   Problem   = (const int*)d_in[0];
    const int*   LF        = (const int*)d_in[1];
    const float* enc_embed = (const float*)d_in[2];
    const float* dec_embed = (const float*)d_in[3];
    const float* enc_Wih_f = (const float*)d_in[4];
    const float* enc_Whh_f = (const float*)d_in[5];
    const float* enc_b_f   = (const float*)d_in[6];
    const float* enc_Wih_b = (const float*)d_in[7];
    const float* enc_Whh_b = (const float*)d_in[8];
    const float* enc_b_b   = (const float*)d_in[9];
    const float* Wh        = (const float*)d_in[10];
    const float* bh        = (const float*)d_in[11];
    const float* Wc        = (const float*)d_in[12];
    const float* bc        = (const float*)d_in[13];
    const float* dec_Wih   = (const float*)d_in[14];
    const float* dec_Whh   = (const float*)d_in[15];
    const float* dec_b     = (const float*)d_in[16];
    const float* fc_W      = (const float*)d_in[17];
    const float* fc_b      = (const float*)d_in[18];
    float* out = (float*)d_out;

    k_idx<<<12, 256>>>(Problem, LF);
    k_zero_t0<<<(Bz * Vv + 255) / 256, 256>>>(out);
    {
        dim3 g(312, 1, 3);
        k_permX<<<g, 256>>>(enc_embed, dec_embed);
    }
    {
        dim3 g(208, 1, 3);
        k_permWih<<<g, 256>>>(enc_Wih_f, enc_Wih_b, dec_Wih);
    }
    {
        dim3 g(XN / 128, XM / 128, 3);
        k_xg<<<g, 256>>>(enc_b_f, enc_b_b, dec_b);
    }

    k_enc_scan<<<128, 512>>>(enc_Whh_f, enc_Whh_b);
    k_h0c0<<<64, 256>>>(Wh, bh, Wc, bc);
    k_dec_scan<<<128, 512>>>(dec_Whh);
    {
        dim3 g(VPAD / 64, Hh / 64);         // 472 x 8
        k_permW<<<g, 256>>>(fc_W);
    }

    {
        dim3 g(VPAD / 256, MPAD / 128);     // 118 x 24
        k_logits_h<<<g, 512>>>(fc_b, out);
    }
}

// round 15
// speedup vs baseline: 1.0065x; 1.0065x over previous
#include <cuda_runtime.h>
#include <cuda_fp16.h>
#include <math.h>
#include <stdint.h>

#define Bz 32
#define Ss 96
#define Tt 96
#define Ee 200
#define Hh 512
#define Vv 30000
#define G4 2048
#define VPAD 30208   // 118 * 256
#define MPAD 3072    // 24 * 128
#define XM 3072
#define XN 2048
#define XK 200
#define NKS 13       // ceil(200/16)

typedef unsigned long long ull;

// Pair layout for (k,b) arrays: element (k,b) at [(k*16+(b&15))*2 + (b>>4)]
__device__ float d_gxf[(size_t)Ss * G4 * Bz];
__device__ float d_gxb[(size_t)Ss * G4 * Bz];
__device__ float d_gxd[(size_t)(Tt - 1) * G4 * Bz];
__device__ float d_hping[2 * 2 * Hh * Bz];
__device__ float d_hdping[2 * Hh * Bz];
__device__ float d_hfin[2 * Hh * Bz];
__device__ float d_cfin[2 * Hh * Bz];
__device__ float d_c0[Hh * Bz];
// fp16 fragment buffers
__device__ uint4 d_ahf[(size_t)MPAD * Hh / 8];   // decoder h, m16n8k16 A-frag
__device__ uint4 d_whf[(size_t)VPAD * Hh / 8];   // fc_W, m16n8k16 B-frag
// x-gemm fp16 hi/lo fragment buffers
__device__ uint4 d_x16ah[3][48 * 4 * NKS * 32];
__device__ uint4 d_x16al[3][48 * 4 * NKS * 32];
__device__ uint4 d_x16bh[3][64 * NKS * 2 * 32];
__device__ uint4 d_x16bl[3][64 * NKS * 2 * 32];
__device__ int d_idxf[Ss * Bz];
__device__ int d_idxb[Ss * Bz];
__device__ int d_idxd[(Tt - 1) * Bz];
__device__ ull d_lf_enc[8 * 16];
__device__ ull d_rt_enc2[32];
__device__ ull d_lf_dec[8 * 16];
__device__ ull d_rt_dec;

__device__ __forceinline__ ull pack2(float x, float y) {
    ull r; asm("mov.b64 %0,{%1,%2};" : "=l"(r) : "f"(x), "f"(y)); return r;
}
__device__ __forceinline__ ull ffma2(ull a, ull b, ull c) {
    ull d; asm("fma.rn.f32x2 %0,%1,%2,%3;" : "=l"(d) : "l"(a), "l"(b), "l"(c)); return d;
}
__device__ __forceinline__ ull fadd2(ull a, ull b) {
    ull d; asm("add.rn.f32x2 %0,%1,%2;" : "=l"(d) : "l"(a), "l"(b)); return d;
}

__device__ __forceinline__ void grid_sync2(ull* leaf, ull* root, int lbid, int nleaf) {
    __syncthreads();
    if (threadIdx.x == 0) {
        __threadfence();
        ull a = atomicAdd(&leaf[(lbid >> 4) * 16], 1ULL) + 1ULL;
        ull phase = (a - 1ULL) >> 4;
        if ((a & 15ULL) == 0ULL) atomicAdd(root, 1ULL);
        ull target = (phase + 1ULL) * (ull)nleaf;
        while (*((volatile ull*)root) < target) { }
        __threadfence();
    }
    __syncthreads();
}

__device__ __forceinline__ void split_h2(float x0, float x1, unsigned& hi, unsigned& lo) {
    __half h0 = __float2half_rn(x0), h1 = __float2half_rn(x1);
    __half l0 = __float2half_rn(x0 - __half2float(h0));
    __half l1 = __float2half_rn(x1 - __half2float(h1));
    __half2 hh = __halves2half2(h0, h1), ll = __halves2half2(l0, l1);
    hi = *(unsigned*)&hh; lo = *(unsigned*)&ll;
}

// launch 0: indices + d_ahf pad zero + output t=0 zero slice (merged)
__global__ void k_idx(const int* __restrict__ Problem, const int* __restrict__ LF,
                      float* __restrict__ out) {
    long m = (long)blockIdx.x * blockDim.x + threadIdx.x;
    if (m < Ss * Bz) {
        int s = (int)m >> 5, b = (int)m & 31;
        d_idxf[m] = Problem[b * Ss + s];
        d_idxb[m] = Problem[b * Ss + (Ss - 1 - s)];
    }
    if (m < (Tt - 1) * Bz) {
        int t = (int)m >> 5, b = (int)m & 31;
        d_idxd[m] = LF[b * Tt + t];
    }
    if (m < 4096) {
        d_ahf[(size_t)47 * 4096 + m] = make_uint4(0u, 0u, 0u, 0u);
    }
    if (m < (long)Bz * Vv) {
        long b = m / Vv;
        long n = m - b * Vv;
        out[b * (long)Tt * Vv + n] = 0.f;
    }
}

// launch 1: all operand perms for the x-gate GEMMs (z in [0,6))
//   z<3: gathered embeddings -> fp16 hi/lo A-fragments (312 blocks used)
//   z>=3: Wih -> fp16 hi/lo B-fragments (208 blocks used)
__global__ void __launch_bounds__(256) k_perm_all(const float* __restrict__ Eenc,
                                                  const float* __restrict__ Edec,
                                                  const float* __restrict__ W0,
                                                  const float* __restrict__ W1,
                                                  const float* __restrict__ W2) {
    int z = blockIdx.z;
    if (z < 3) {
        int which = z;
        int Mlim = (which == 2) ? 3040 : XM;
        const float* E = (which == 2) ? Edec : Eenc;
        const int* ridx = (which == 0) ? d_idxf : (which == 1) ? d_idxb : d_idxd;
        int o = blockIdx.x * 256 + threadIdx.x;   // < 79872
        int lane = o & 31;
        int t = o >> 5;
        int ks = t % NKS;
        int t2 = t / NKS;
        int mt = t2 & 3, wt = t2 >> 2;
        int kb = ks * 16 + (lane & 3) * 2;
        int mrow = wt * 64 + mt * 16 + (lane >> 2);
        unsigned hic[4], loc[4];
#pragma unroll
        for (int c = 0; c < 4; c++) {
            int hi8 = c & 1, khi = c >> 1;
            int m = mrow + hi8 * 8;
            int k = kb + khi * 8;
            float v0 = 0.f, v1 = 0.f;
            if (m < Mlim && k < XK) {
                const float* r = E + (size_t)ridx[m] * XK;
                v0 = r[k];
                if (k + 1 < XK) v1 = r[k + 1];
            }
            split_h2(v0, v1, hic[c], loc[c]);
        }
        d_x16ah[which][o] = make_uint4(hic[0], hic[1], hic[2], hic[3]);
        d_x16al[which][o] = make_uint4(loc[0], loc[1], loc[2], loc[3]);
    } else {
        if (blockIdx.x >= 208) return;
        int which = z - 3;
        const float* W = (which == 0) ? W0 : (which == 1) ? W1 : W2;
        int o = blockIdx.x * 256 + threadIdx.x;   // < 53248
        int lane = o & 31;
        int q2 = (o >> 5) & 1;
        int t = o >> 6;
        int ks = t % NKS;
        int nt = t / NKS;
        unsigned hic[4], loc[4];
#pragma unroll
        for (int c = 0; c < 4; c++) {
            int sub = c >> 1, khi = c & 1;
            int n = nt * 32 + (q2 * 2 + sub) * 8 + (lane >> 2);
            int k = ks * 16 + khi * 8 + (lane & 3) * 2;
            float v0 = 0.f, v1 = 0.f;
            if (k < XK) {
                v0 = W[(size_t)n * XK + k];
                if (k + 1 < XK) v1 = W[(size_t)n * XK + k + 1];
            }
            split_h2(v0, v1, hic[c], loc[c]);
        }
        d_x16bh[which][o] = make_uint4(hic[0], hic[1], hic[2], hic[3]);
        d_x16bl[which][o] = make_uint4(loc[0], loc[1], loc[2], loc[3]);
    }
}

// ---- permW v2: smem-tiled, coalesced. grid (472, 8) -----------------------
__global__ void __launch_bounds__(256) k_permW(const float* __restrict__ W) {
    __shared__ float sw[64][65];
    int tid = threadIdx.x;
    int n0 = blockIdx.x * 64;
    int k0 = blockIdx.y * 64;
    for (int i = tid; i < 1024; i += 256) {
        int row = i >> 4, f4 = i & 15;
        float4 v = make_float4(0.f, 0.f, 0.f, 0.f);
        if (n0 + row < Vv)
            v = *(const float4*)(W + (size_t)(n0 + row) * Hh + k0 + f4 * 4);
        sw[row][f4 * 4 + 0] = v.x; sw[row][f4 * 4 + 1] = v.y;
        sw[row][f4 * 4 + 2] = v.z; sw[row][f4 * 4 + 3] = v.w;
    }
    __syncthreads();
    for (int e = tid; e < 512; e += 256) {
        int lane = e & 31, q = (e >> 5) & 3, ksl = (e >> 7) & 3;
        unsigned comp[4];
#pragma unroll
        for (int c = 0; c < 4; c++) {
            int sub = c >> 1, khi = c & 1;
            int nl = (q * 2 + sub) * 8 + (lane >> 2);
            int kl = ksl * 16 + khi * 8 + (lane & 3) * 2;
            __half2 h2 = __floats2half2_rn(sw[nl][kl], sw[nl][kl + 1]);
            comp[c] = *(unsigned*)&h2;
        }
        int ks_g = blockIdx.y * 4 + ksl;
        d_whf[(size_t)blockIdx.x * 4096 + ks_g * 128 + q * 32 + lane]
            = make_uint4(comp[0], comp[1], comp[2], comp[3]);
    }
}

#define MMA_F16(c0, c1, c2, c3, A0, A1, A2, A3, B0, B1) \
    asm volatile( \
        "mma.sync.aligned.m16n8k16.row.col.f32.f16.f16.f32 " \
        "{%0,%1,%2,%3},{%4,%5,%6,%7},{%8,%9},{%0,%1,%2,%3};" \
        : "+f"(c0), "+f"(c1), "+f"(c2), "+f"(c3) \
        : "r"(A0), "r"(A1), "r"(A2), "r"(A3), "r"(B0), "r"(B1))

// ---- x-gate GEMMs, fp16 hi/lo 3-term ---------------------------------------
__global__ void __launch_bounds__(256) k_xg(const float* __restrict__ bias0,
                                            const float* __restrict__ bias1,
                                            const float* __restrict__ bias2) {
    int which = blockIdx.z;
    const float* bias = (which == 0) ? bias0 : (which == 1) ? bias1 : bias2;
    int Mlim = (which == 2) ? 3040 : XM;
    float* out = (which == 0) ? d_gxf : (which == 1) ? d_gxb : d_gxd;
    int tid = threadIdx.x, w = tid >> 5, lane = tid & 31;
    int wm = w & 1, wn = w >> 1;
    int wt = blockIdx.y * 2 + wm;
    int nt = blockIdx.x * 4 + wn;
    const uint4* Ah = d_x16ah[which] + (size_t)wt * 4 * NKS * 32 + lane;
    const uint4* Al = d_x16al[which] + (size_t)wt * 4 * NKS * 32 + lane;
    const uint4* Bh = d_x16bh[which] + (size_t)nt * NKS * 2 * 32 + lane;
    const uint4* Bl = d_x16bl[which] + (size_t)nt * NKS * 2 * 32 + lane;

    float acc[4][4][4];
#pragma unroll
    for (int a = 0; a < 4; a++)
#pragma unroll
        for (int b = 0; b < 4; b++)
#pragma unroll
            for (int cc = 0; cc < 4; cc++) acc[a][b][cc] = 0.f;

    for (int ks = 0; ks < NKS; ks++) {
        uint4 ah[4], al[4], bh[2], bl[2];
#pragma unroll
        for (int mt = 0; mt < 4; mt++) {
            ah[mt] = Ah[(mt * NKS + ks) * 32];
            al[mt] = Al[(mt * NKS + ks) * 32];
        }
#pragma unroll
        for (int q2 = 0; q2 < 2; q2++) {
            bh[q2] = Bh[(ks * 2 + q2) * 32];
            bl[q2] = Bl[(ks * 2 + q2) * 32];
        }
#pragma unroll
        for (int mt = 0; mt < 4; mt++) {
#pragma unroll
            for (int n8 = 0; n8 < 4; n8++) {
                int q2 = n8 >> 1, sub = n8 & 1;
                unsigned bh0 = sub ? bh[q2].z : bh[q2].x;
                unsigned bh1 = sub ? bh[q2].w : bh[q2].y;
                unsigned bl0 = sub ? bl[q2].z : bl[q2].x;
                unsigned bl1 = sub ? bl[q2].w : bl[q2].y;
                MMA_F16(acc[mt][n8][0], acc[mt][n8][1], acc[mt][n8][2], acc[mt][n8][3],
                        ah[mt].x, ah[mt].y, ah[mt].z, ah[mt].w, bh0, bh1);
                MMA_F16(acc[mt][n8][0], acc[mt][n8][1], acc[mt][n8][2], acc[mt][n8][3],
                        ah[mt].x, ah[mt].y, ah[mt].z, ah[mt].w, bl0, bl1);
                MMA_F16(acc[mt][n8][0], acc[mt][n8][1], acc[mt][n8][2], acc[mt][n8][3],
                        al[mt].x, al[mt].y, al[mt].z, al[mt].w, bh0, bh1);
            }
        }
    }

    int mb = blockIdx.y * 128 + wm * 64;
    int nb = blockIdx.x * 128 + wn * 32;
#pragma unroll
    for (int mt = 0; mt < 4; mt++) {
        int r0 = mb + mt * 16 + (lane >> 2);
#pragma unroll
        for (int n8 = 0; n8 < 4; n8++) {
            int n = nb + n8 * 8 + (lane & 3) * 2;
            float b0 = bias[n], b1 = bias[n + 1];
#pragma unroll
            for (int rh = 0; rh < 2; rh++) {
                int m = r0 + rh * 8;
                if (m < Mlim) {
                    size_t base = ((size_t)(m >> 5) * XN + n) * 32 + (m & 15) * 2 + ((m >> 4) & 1);
                    out[base]      = acc[mt][n8][rh * 2 + 0] + b0;
                    out[base + 32] = acc[mt][n8][rh * 2 + 1] + b1;
                }
            }
        }
    }
}

__device__ __forceinline__ void lstm_cell(float ai, float af, float ag, float ao,
                                          float& c, float& h) {
    float si = 1.f / (1.f + expf(-ai));
    float sf = 1.f / (1.f + expf(-af));
    float so = 1.f / (1.f + expf(-ao));
    float tg = tanhf(ag);
    c = sf * c + si * tg;
    h = so * tanhf(c);
}

#define HS_ROW 9

// =====================================================================
// enc scan: 128 blocks x 512 threads. blocks[0,64)=fwd, [64,128)=bwd.
// 8 j/block; 2 warps per j.
// =====================================================================
__global__ void __launch_bounds__(512) k_enc_scan(const float* __restrict__ Whf,
                                                  const float* __restrict__ Whb) {
    __shared__ float4 hsh4[256 * HS_ROW];
    __shared__ ull gsh[8][2][4][8];
    int tid = threadIdx.x, w = tid >> 5, lane = tid & 31;
    int g = lane & 3, kc = lane >> 2;
    int jl = w >> 1, bhalf = w & 1;
    int dir = blockIdx.x >> 6;
    int j = (blockIdx.x & 63) * 8 + jl;
    int pq = lane & 7, chalf = (lane >> 3) & 1;
    int bp = bhalf * 8 + pq;
    bool cell_lane = (lane < 16);

    const float* gx = dir ? d_gxb : d_gxf;
    const float* Whh = dir ? Whb : Whf;
    float* hbuf = d_hping + (size_t)dir * (2 * Hh * Bz);
    ull* lf = d_lf_enc + dir * 64;
    ull* rt = &d_rt_enc2[dir * 16];

    float wreg[64];
    {
        const float* wrow = Whh + ((size_t)g * Hh + j) * Hh + kc;
#pragma unroll
        for (int kk = 0; kk < 64; kk++) wreg[kk] = wrow[kk * 8];
    }
    float c = 0.f, h = 0.f;

    for (int s = 0; s < Ss; s++) {
        float ga0 = 0.f, ga1 = 0.f, ga2 = 0.f, ga3 = 0.f;
        if (cell_lane) {
            const float* gxs = gx + (size_t)s * G4 * Bz;
            ga0 = gxs[(0 * Hh + j) * Bz + bp * 2 + chalf];
            ga1 = gxs[(1 * Hh + j) * Bz + bp * 2 + chalf];
            ga2 = gxs[(2 * Hh + j) * Bz + bp * 2 + chalf];
            ga3 = gxs[(3 * Hh + j) * Bz + bp * 2 + chalf];
        }

        if (s > 0) {
            ull acc[8];
#pragma unroll
            for (int i = 0; i < 8; i++) acc[i] = 0ULL;
            const float4* src = (const float4*)(hbuf + (size_t)(s & 1) * (Hh * Bz));
#pragma unroll
            for (int ch = 0; ch < 2; ch++) {
                for (int ii = tid; ii < 2048; ii += 512)
                    hsh4[(ii >> 3) * HS_ROW + (ii & 7)] = src[ch * 2048 + ii];
                __syncthreads();
                const ulonglong2* hs2 = (const ulonglong2*)hsh4;
#pragma unroll
                for (int kk2 = 0; kk2 < 32; kk2++) {
                    float wv = wreg[ch * 32 + kk2];
                    ull w2 = pack2(wv, wv);
                    const ulonglong2* row = hs2 + (kc + (kk2 << 3)) * HS_ROW + bhalf * 4;
#pragma unroll
                    for (int bq = 0; bq < 4; bq++) {
                        ulonglong2 hv = row[bq];
                        acc[2 * bq]     = ffma2(w2, hv.x, acc[2 * bq]);
                        acc[2 * bq + 1] = ffma2(w2, hv.y, acc[2 * bq + 1]);
                    }
                }
                __syncthreads();
            }
#pragma unroll
            for (int i = 0; i < 8; i++) {
                acc[i] = fadd2(acc[i], __shfl_xor_sync(0xffffffffu, acc[i], 4));
                acc[i] = fadd2(acc[i], __shfl_xor_sync(0xffffffffu, acc[i], 8));
                acc[i] = fadd2(acc[i], __shfl_xor_sync(0xffffffffu, acc[i], 16));
            }
            if (lane < 4) {
#pragma unroll
                for (int i = 0; i < 8; i++) gsh[jl][bhalf][lane][i] = acc[i];
            }
            __syncwarp();
            if (cell_lane) {
                const float* gsf = (const float*)&gsh[jl][bhalf][0][0];
                ga0 += gsf[(0 * 8 + pq) * 2 + chalf];
                ga1 += gsf[(1 * 8 + pq) * 2 + chalf];
                ga2 += gsf[(2 * 8 + pq) * 2 + chalf];
                ga3 += gsf[(3 * 8 + pq) * 2 + chalf];
            }
            __syncwarp();
        }
        if (cell_lane) {
            lstm_cell(ga0, ga1, ga2, ga3, c, h);
            hbuf[(size_t)((s + 1) & 1) * (Hh * Bz) + (j * 16 + bp) * 2 + chalf] = h;
        }
        grid_sync2(lf, rt, blockIdx.x & 63, 4);
    }
    if (cell_lane) {
        d_hfin[(size_t)dir * (Hh * Bz) + (j * 16 + bp) * 2 + chalf] = h;
        d_cfin[(size_t)dir * (Hh * Bz) + (j * 16 + bp) * 2 + chalf] = c;
    }
}

// =====================================================================
// dec scan: 128 blocks x 512 threads. 4 j/block; 4 warps per j.
// =====================================================================
__global__ void __launch_bounds__(512) k_dec_scan(const float* __restrict__ Whh) {
    __shared__ float4 hsh4[256 * HS_ROW];
    __shared__ ull gsh[4][4][4][4];
    int tid = threadIdx.x, w = tid >> 5, lane = tid & 31;
    int g = lane & 3, kc = lane >> 2;
    int jl = w >> 2, bq4 = w & 3;
    int j = blockIdx.x * 4 + jl;
    int pq = lane & 3, chalf = (lane >> 2) & 1;
    int bp = bq4 * 4 + pq;
    bool cell_lane = (lane < 8);

    float wreg[64];
    {
        const float* wrow = Whh + ((size_t)g * Hh + j) * Hh + kc;
#pragma unroll
        for (int kk = 0; kk < 64; kk++) wreg[kk] = wrow[kk * 8];
    }
    float c = cell_lane ? d_c0[(j * 16 + bp) * 2 + chalf] : 0.f;
    float h = 0.f;

    int ks_j = j >> 4;
    int khi_j = (j >> 3) & 1;
    int tig_j = (j & 7) >> 1;
    int kpar_j = j & 1;

    for (int t = 0; t < Tt - 1; t++) {
        float ga0 = 0.f, ga1 = 0.f, ga2 = 0.f, ga3 = 0.f;
        if (cell_lane) {
            const float* gxs = d_gxd + (size_t)t * G4 * Bz;
            ga0 = gxs[(0 * Hh + j) * Bz + bp * 2 + chalf];
            ga1 = gxs[(1 * Hh + j) * Bz + bp * 2 + chalf];
            ga2 = gxs[(2 * Hh + j) * Bz + bp * 2 + chalf];
            ga3 = gxs[(3 * Hh + j) * Bz + bp * 2 + chalf];
        }

        ull acc[4];
#pragma unroll
        for (int i = 0; i < 4; i++) acc[i] = 0ULL;
        const float4* src = (const float4*)(d_hdping + (size_t)(t & 1) * (Hh * Bz));
#pragma unroll
        for (int ch = 0; ch < 2; ch++) {
            for (int ii = tid; ii < 2048; ii += 512)
                hsh4[(ii >> 3) * HS_ROW + (ii & 7)] = src[ch * 2048 + ii];
            __syncthreads();
            const ulonglong2* hs2 = (const ulonglong2*)hsh4;
#pragma unroll
            for (int kk2 = 0; kk2 < 32; kk2++) {
                float wv = wreg[ch * 32 + kk2];
                ull w2 = pack2(wv, wv);
                const ulonglong2* row = hs2 + (kc + (kk2 << 3)) * HS_ROW + bq4 * 2;
#pragma unroll
                for (int bq = 0; bq < 2; bq++) {
                    ulonglong2 hv = row[bq];
                    acc[2 * bq]     = ffma2(w2, hv.x, acc[2 * bq]);
                    acc[2 * bq + 1] = ffma2(w2, hv.y, acc[2 * bq + 1]);
                }
            }
            __syncthreads();
        }
#pragma unroll
        for (int i = 0; i < 4; i++) {
            acc[i] = fadd2(acc[i], __shfl_xor_sync(0xffffffffu, acc[i], 4));
            acc[i] = fadd2(acc[i], __shfl_xor_sync(0xffffffffu, acc[i], 8));
            acc[i] = fadd2(acc[i], __shfl_xor_sync(0xffffffffu, acc[i], 16));
        }
        if (lane < 4) {
#pragma unroll
            for (int i = 0; i < 4; i++) gsh[jl][bq4][lane][i] = acc[i];
        }
        __syncwarp();
        if (cell_lane) {
            const float* gsf = (const float*)&gsh[jl][bq4][0][0];
            ga0 += gsf[(0 * 4 + pq) * 2 + chalf];
            ga1 += gsf[(1 * 4 + pq) * 2 + chalf];
            ga2 += gsf[(2 * 4 + pq) * 2 + chalf];
            ga3 += gsf[(3 * 4 + pq) * 2 + chalf];
            lstm_cell(ga0, ga1, ga2, ga3, c, h);
            d_hdping[(size_t)((t + 1) & 1) * (Hh * Bz) + (j * 16 + bp) * 2 + chalf] = h;
            int mrow = t * 32 + bp + 16 * chalf;
            int chunk = mrow >> 6;
            int mt = (mrow >> 4) & 3;
            int row16 = mrow & 15;
            int ga = row16 & 7, hi8 = row16 >> 3;
            int lane_f = ga * 4 + tig_j;
            int comp = hi8 + 2 * khi_j;
            size_t hidx = (((size_t)chunk * 4096 + ks_j * 128 + mt * 32 + lane_f) * 4
                           + comp) * 2 + kpar_j;
            ((__half*)d_ahf)[hidx] = __float2half_rn(h);
        }
        grid_sync2(d_lf_dec, &d_rt_dec, blockIdx.x, 8);
    }
}

__global__ void __launch_bounds__(256) k_h0c0(const float* __restrict__ Wh,
                                              const float* __restrict__ bh,
                                              const float* __restrict__ Wc,
                                              const float* __restrict__ bc) {
    int gg = blockIdx.x * blockDim.x + threadIdx.x;
    int j = gg >> 5, b = gg & 31;
    int bp = b & 15, hf = b >> 4;
    const float* hfp = d_hfin + bp * 2 + hf;
    const float* cfp = d_cfin + bp * 2 + hf;
    const float* whr = Wh + (size_t)j * (2 * Hh);
    const float* wcr = Wc + (size_t)j * (2 * Hh);
    float ah = bh[j], ac = bc[j];
#pragma unroll 8
    for (int k = 0; k < 2 * Hh; k++) {
        ah += whr[k] * hfp[k * 32];
        ac += wcr[k] * cfp[k * 32];
    }
    d_hdping[(j * 16 + bp) * 2 + hf] = ah;
    d_c0[(j * 16 + bp) * 2 + hf] = ac;
}

// Logits: fp16 m16n8k16. CTA 128m x 256n, 512 threads, warp 64x32.
__global__ void __launch_bounds__(512, 1) k_logits_h(const float* __restrict__ fcb,
                                                     float* __restrict__ out) {
    int tid = threadIdx.x, w = tid >> 5, lane = tid & 31;
    int wm = w & 1, wn = w >> 1;
    int mtile = blockIdx.y, ntile = blockIdx.x;

    const uint4* Ab = d_ahf + (size_t)(mtile * 2 + wm) * 4096 + lane;
    const uint4* Bb = d_whf + (size_t)(ntile * 4 + (wn >> 1)) * 4096
                      + (wn & 1) * 64 + lane;

    float acc[4][4][4];
#pragma unroll
    for (int a = 0; a < 4; a++)
#pragma unroll
        for (int b = 0; b < 4; b++)
#pragma unroll
            for (int cc = 0; cc < 4; cc++) acc[a][b][cc] = 0.f;

    uint4 av[2][4], bv[2][2];
#pragma unroll
    for (int q = 0; q < 4; q++) av[0][q] = Ab[q * 32];
#pragma unroll
    for (int p = 0; p < 2; p++) bv[0][p] = Bb[p * 32];

    for (int ks = 0; ks < 32; ks++) {
        int cur = ks & 1, nxt = cur ^ 1;
        if (ks < 31) {
            const uint4* An = Ab + (ks + 1) * 128;
            const uint4* Bn = Bb + (ks + 1) * 128;
#pragma unroll
            for (int q = 0; q < 4; q++) av[nxt][q] = An[q * 32];
#pragma unroll
            for (int p = 0; p < 2; p++) bv[nxt][p] = Bn[p * 32];
        }
#pragma unroll
        for (int mt = 0; mt < 4; mt++) {
            unsigned a0 = av[cur][mt].x, a1 = av[cur][mt].y;
            unsigned a2 = av[cur][mt].z, a3 = av[cur][mt].w;
#pragma unroll
            for (int p = 0; p < 2; p++) {
                MMA_F16(acc[mt][2 * p][0], acc[mt][2 * p][1],
                        acc[mt][2 * p][2], acc[mt][2 * p][3],
                        a0, a1, a2, a3, bv[cur][p].x, bv[cur][p].y);
                MMA_F16(acc[mt][2 * p + 1][0], acc[mt][2 * p + 1][1],
                        acc[mt][2 * p + 1][2], acc[mt][2 * p + 1][3],
                        a0, a1, a2, a3, bv[cur][p].z, bv[cur][p].w);
            }
        }
    }

    int mb = mtile * 128 + wm * 64;
    int nb = ntile * 256 + wn * 32;
#pragma unroll
    for (int mt = 0; mt < 4; mt++) {
        int r0 = mb + mt * 16 + (lane >> 2);
#pragma unroll
        for (int nt = 0; nt < 4; nt++) {
            int n = nb + nt * 8 + (lane & 3) * 2;
            if (n >= Vv) continue;
            float b0 = fcb[n];
            float b1 = fcb[n + 1];
#pragma unroll
            for (int rh = 0; rh < 2; rh++) {
                int m = r0 + rh * 8;
                if (m < 3040) {
                    int b = m & 31, ts = m >> 5;
                    size_t o = ((size_t)b * Tt + ts + 1) * (size_t)Vv + n;
                    out[o]     = acc[mt][nt][rh * 2 + 0] + b0;
                    out[o + 1] = acc[mt][nt][rh * 2 + 1] + b1;
                }
            }
        }
    }
}

extern "C" void kernel_launch(void* const* d_in, const int* in_sizes, int n_in,
                              void* d_out, int out_size) {
    (void)in_sizes; (void)n_in; (void)out_size;
    const int*   Problem   = (const int*)d_in[0];
    const int*   LF        = (const int*)d_in[1];
    const float* enc_embed = (const float*)d_in[2];
    const float* dec_embed = (const float*)d_in[3];
    const float* enc_Wih_f = (const float*)d_in[4];
    const float* enc_Whh_f = (const float*)d_in[5];
    const float* enc_b_f   = (const float*)d_in[6];
    const float* enc_Wih_b = (const float*)d_in[7];
    const float* enc_Whh_b = (const float*)d_in[8];
    const float* enc_b_b   = (const float*)d_in[9];
    const float* Wh        = (const float*)d_in[10];
    const float* bh        = (const float*)d_in[11];
    const float* Wc        = (const float*)d_in[12];
    const float* bc        = (const float*)d_in[13];
    const float* dec_Wih   = (const float*)d_in[14];
    const float* dec_Whh   = (const float*)d_in[15];
    const float* dec_b     = (const float*)d_in[16];
    const float* fc_W      = (const float*)d_in[17];
    const float* fc_b      = (const float*)d_in[18];
    float* out = (float*)d_out;

    // launch 0: indices + pad zero + t0 zero (merged)
    k_idx<<<(Bz * Vv + 255) / 256, 256>>>(Problem, LF, out);
    // launch 1: all x-gemm operand perms
    {
        dim3 g(312, 1, 6);
        k_perm_all<<<g, 256>>>(enc_embed, dec_embed, enc_Wih_f, enc_Wih_b, dec_Wih);
    }
    // launch 2: x-gate GEMMs
    {
        dim3 g(XN / 128, XM / 128, 3);
        k_xg<<<g, 256>>>(enc_b_f, enc_b_b, dec_b);
    }

    k_enc_scan<<<128, 512>>>(enc_Whh_f, enc_Whh_b);     // launch 3 <- profiled?
    k_h0c0<<<64, 256>>>(Wh, bh, Wc, bc);                // 4
    k_dec_scan<<<128, 512>>>(dec_Whh);                  // 5
    {
        dim3 g(VPAD / 64, Hh / 64);                     // 6
        k_permW<<<g, 256>>>(fc_W);
    }
    {
        dim3 g(VPAD / 256, MPAD / 128);                 // 7
        k_logits_h<<<g, 512>>>(fc_b, out);
    }
}

// round 16
// speedup vs baseline: 1.0126x; 1.0060x over previous
#include <cuda_runtime.h>
#include <cuda_fp16.h>
#include <math.h>
#include <stdint.h>

#define Bz 32
#define Ss 96
#define Tt 96
#define Ee 200
#define Hh 512
#define Vv 30000
#define G4 2048
#define VPAD 30208   // 118 * 256
#define MPAD 3072    // 24 * 128
#define XM 3072
#define XN 2048
#define XK 200
#define NKS 13       // ceil(200/16)

typedef unsigned long long ull;

// Pair layout for (k,b) arrays: element (k,b) at [(k*16+(b&15))*2 + (b>>4)]
__device__ float d_gxf[(size_t)Ss * G4 * Bz];
__device__ float d_gxb[(size_t)Ss * G4 * Bz];
__device__ float d_gxd[(size_t)(Tt - 1) * G4 * Bz];
__device__ float d_hping[2 * 2 * Hh * Bz];
__device__ float d_hdping[2 * Hh * Bz];
__device__ float d_hfin[2 * Hh * Bz];
__device__ float d_cfin[2 * Hh * Bz];
__device__ float d_c0[Hh * Bz];
// fp16 fragment buffers
__device__ uint4 d_ahf[(size_t)MPAD * Hh / 8];   // decoder h, m16n8k16 A-frag
__device__ uint4 d_whf[(size_t)VPAD * Hh / 8];   // fc_W, m16n8k16 B-frag
// x-gemm fp16 hi/lo fragment buffers
__device__ uint4 d_x16ah[3][48 * 4 * NKS * 32];
__device__ uint4 d_x16al[3][48 * 4 * NKS * 32];
__device__ uint4 d_x16bh[3][64 * NKS * 2 * 32];
__device__ uint4 d_x16bl[3][64 * NKS * 2 * 32];
__device__ int d_idxf[Ss * Bz];
__device__ int d_idxb[Ss * Bz];
__device__ int d_idxd[(Tt - 1) * Bz];
__device__ ull d_lf_enc[8 * 16];
__device__ ull d_rt_enc2[32];
__device__ ull d_lf_dec[8 * 16];
__device__ ull d_rt_dec;

__device__ __forceinline__ ull pack2(float x, float y) {
    ull r; asm("mov.b64 %0,{%1,%2};" : "=l"(r) : "f"(x), "f"(y)); return r;
}
__device__ __forceinline__ ull ffma2(ull a, ull b, ull c) {
    ull d; asm("fma.rn.f32x2 %0,%1,%2,%3;" : "=l"(d) : "l"(a), "l"(b), "l"(c)); return d;
}
__device__ __forceinline__ ull fadd2(ull a, ull b) {
    ull d; asm("add.rn.f32x2 %0,%1,%2;" : "=l"(d) : "l"(a), "l"(b)); return d;
}

// Fence-free grid barrier: release-atomics publish, acquire-load subscribes.
// No membar.gl (no L1D flush). Monotone counters -> graph-replay safe.
__device__ __forceinline__ void grid_sync2(ull* leaf, ull* root, int lbid, int nleaf) {
    __syncthreads();
    if (threadIdx.x == 0) {
        ull a;
        asm volatile("atom.add.release.gpu.u64 %0, [%1], 1;"
                     : "=l"(a) : "l"(leaf + (lbid >> 4) * 16) : "memory");
        a += 1ULL;
        ull phase = (a - 1ULL) >> 4;
        if ((a & 15ULL) == 0ULL)
            asm volatile("red.add.release.gpu.u64 [%0], 1;" :: "l"(root) : "memory");
        ull target = (phase + 1ULL) * (ull)nleaf;
        ull v;
        do {
            asm volatile("ld.acquire.gpu.u64 %0, [%1];" : "=l"(v) : "l"(root) : "memory");
        } while (v < target);
    }
    __syncthreads();
}

__device__ __forceinline__ void split_h2(float x0, float x1, unsigned& hi, unsigned& lo) {
    __half h0 = __float2half_rn(x0), h1 = __float2half_rn(x1);
    __half l0 = __float2half_rn(x0 - __half2float(h0));
    __half l1 = __float2half_rn(x1 - __half2float(h1));
    __half2 hh = __halves2half2(h0, h1), ll = __halves2half2(l0, l1);
    hi = *(unsigned*)&hh; lo = *(unsigned*)&ll;
}

// launch 0: indices + d_ahf pad zero + output t=0 zero slice (merged)
__global__ void k_idx(const int* __restrict__ Problem, const int* __restrict__ LF,
                      float* __restrict__ out) {
    long m = (long)blockIdx.x * blockDim.x + threadIdx.x;
    if (m < Ss * Bz) {
        int s = (int)m >> 5, b = (int)m & 31;
        d_idxf[m] = Problem[b * Ss + s];
        d_idxb[m] = Problem[b * Ss + (Ss - 1 - s)];
    }
    if (m < (Tt - 1) * Bz) {
        int t = (int)m >> 5, b = (int)m & 31;
        d_idxd[m] = LF[b * Tt + t];
    }
    if (m < 4096) {
        d_ahf[(size_t)47 * 4096 + m] = make_uint4(0u, 0u, 0u, 0u);
    }
    if (m < (long)Bz * Vv) {
        long b = m / Vv;
        long n = m - b * Vv;
        out[b * (long)Tt * Vv + n] = 0.f;
    }
}

// launch 1: all operand perms for the x-gate GEMMs (z in [0,6))
__global__ void __launch_bounds__(256) k_perm_all(const float* __restrict__ Eenc,
                                                  const float* __restrict__ Edec,
                                                  const float* __restrict__ W0,
                                                  const float* __restrict__ W1,
                                                  const float* __restrict__ W2) {
    int z = blockIdx.z;
    if (z < 3) {
        int which = z;
        int Mlim = (which == 2) ? 3040 : XM;
        const float* E = (which == 2) ? Edec : Eenc;
        const int* ridx = (which == 0) ? d_idxf : (which == 1) ? d_idxb : d_idxd;
        int o = blockIdx.x * 256 + threadIdx.x;
        int lane = o & 31;
        int t = o >> 5;
        int ks = t % NKS;
        int t2 = t / NKS;
        int mt = t2 & 3, wt = t2 >> 2;
        int kb = ks * 16 + (lane & 3) * 2;
        int mrow = wt * 64 + mt * 16 + (lane >> 2);
        unsigned hic[4], loc[4];
#pragma unroll
        for (int c = 0; c < 4; c++) {
            int hi8 = c & 1, khi = c >> 1;
            int m = mrow + hi8 * 8;
            int k = kb + khi * 8;
            float v0 = 0.f, v1 = 0.f;
            if (m < Mlim && k < XK) {
                const float* r = E + (size_t)ridx[m] * XK;
                v0 = r[k];
                if (k + 1 < XK) v1 = r[k + 1];
            }
            split_h2(v0, v1, hic[c], loc[c]);
        }
        d_x16ah[which][o] = make_uint4(hic[0], hic[1], hic[2], hic[3]);
        d_x16al[which][o] = make_uint4(loc[0], loc[1], loc[2], loc[3]);
    } else {
        if (blockIdx.x >= 208) return;
        int which = z - 3;
        const float* W = (which == 0) ? W0 : (which == 1) ? W1 : W2;
        int o = blockIdx.x * 256 + threadIdx.x;
        int lane = o & 31;
        int q2 = (o >> 5) & 1;
        int t = o >> 6;
        int ks = t % NKS;
        int nt = t / NKS;
        unsigned hic[4], loc[4];
#pragma unroll
        for (int c = 0; c < 4; c++) {
            int sub = c >> 1, khi = c & 1;
            int n = nt * 32 + (q2 * 2 + sub) * 8 + (lane >> 2);
            int k = ks * 16 + khi * 8 + (lane & 3) * 2;
            float v0 = 0.f, v1 = 0.f;
            if (k < XK) {
                v0 = W[(size_t)n * XK + k];
                if (k + 1 < XK) v1 = W[(size_t)n * XK + k + 1];
            }
            split_h2(v0, v1, hic[c], loc[c]);
        }
        d_x16bh[which][o] = make_uint4(hic[0], hic[1], hic[2], hic[3]);
        d_x16bl[which][o] = make_uint4(loc[0], loc[1], loc[2], loc[3]);
    }
}

// ---- permW v2: smem-tiled, coalesced. grid (472, 8) -----------------------
__global__ void __launch_bounds__(256) k_permW(const float* __restrict__ W) {
    __shared__ float sw[64][65];
    int tid = threadIdx.x;
    int n0 = blockIdx.x * 64;
    int k0 = blockIdx.y * 64;
    for (int i = tid; i < 1024; i += 256) {
        int row = i >> 4, f4 = i & 15;
        float4 v = make_float4(0.f, 0.f, 0.f, 0.f);
        if (n0 + row < Vv)
            v = *(const float4*)(W + (size_t)(n0 + row) * Hh + k0 + f4 * 4);
        sw[row][f4 * 4 + 0] = v.x; sw[row][f4 * 4 + 1] = v.y;
        sw[row][f4 * 4 + 2] = v.z; sw[row][f4 * 4 + 3] = v.w;
    }
    __syncthreads();
    for (int e = tid; e < 512; e += 256) {
        int lane = e & 31, q = (e >> 5) & 3, ksl = (e >> 7) & 3;
        unsigned comp[4];
#pragma unroll
        for (int c = 0; c < 4; c++) {
            int sub = c >> 1, khi = c & 1;
            int nl = (q * 2 + sub) * 8 + (lane >> 2);
            int kl = ksl * 16 + khi * 8 + (lane & 3) * 2;
            __half2 h2 = __floats2half2_rn(sw[nl][kl], sw[nl][kl + 1]);
            comp[c] = *(unsigned*)&h2;
        }
        int ks_g = blockIdx.y * 4 + ksl;
        d_whf[(size_t)blockIdx.x * 4096 + ks_g * 128 + q * 32 + lane]
            = make_uint4(comp[0], comp[1], comp[2], comp[3]);
    }
}

#define MMA_F16(c0, c1, c2, c3, A0, A1, A2, A3, B0, B1) \
    asm volatile( \
        "mma.sync.aligned.m16n8k16.row.col.f32.f16.f16.f32 " \
        "{%0,%1,%2,%3},{%4,%5,%6,%7},{%8,%9},{%0,%1,%2,%3};" \
        : "+f"(c0), "+f"(c1), "+f"(c2), "+f"(c3) \
        : "r"(A0), "r"(A1), "r"(A2), "r"(A3), "r"(B0), "r"(B1))

// ---- x-gate GEMMs, fp16 hi/lo 3-term ---------------------------------------
__global__ void __launch_bounds__(256) k_xg(const float* __restrict__ bias0,
                                            const float* __restrict__ bias1,
                                            const float* __restrict__ bias2) {
    int which = blockIdx.z;
    const float* bias = (which == 0) ? bias0 : (which == 1) ? bias1 : bias2;
    int Mlim = (which == 2) ? 3040 : XM;
    float* out = (which == 0) ? d_gxf : (which == 1) ? d_gxb : d_gxd;
    int tid = threadIdx.x, w = tid >> 5, lane = tid & 31;
    int wm = w & 1, wn = w >> 1;
    int wt = blockIdx.y * 2 + wm;
    int nt = blockIdx.x * 4 + wn;
    const uint4* Ah = d_x16ah[which] + (size_t)wt * 4 * NKS * 32 + lane;
    const uint4* Al = d_x16al[which] + (size_t)wt * 4 * NKS * 32 + lane;
    const uint4* Bh = d_x16bh[which] + (size_t)nt * NKS * 2 * 32 + lane;
    const uint4* Bl = d_x16bl[which] + (size_t)nt * NKS * 2 * 32 + lane;

    float acc[4][4][4];
#pragma unroll
    for (int a = 0; a < 4; a++)
#pragma unroll
        for (int b = 0; b < 4; b++)
#pragma unroll
            for (int cc = 0; cc < 4; cc++) acc[a][b][cc] = 0.f;

    for (int ks = 0; ks < NKS; ks++) {
        uint4 ah[4], al[4], bh[2], bl[2];
#pragma unroll
        for (int mt = 0; mt < 4; mt++) {
            ah[mt] = Ah[(mt * NKS + ks) * 32];
            al[mt] = Al[(mt * NKS + ks) * 32];
        }
#pragma unroll
        for (int q2 = 0; q2 < 2; q2++) {
            bh[q2] = Bh[(ks * 2 + q2) * 32];
            bl[q2] = Bl[(ks * 2 + q2) * 32];
        }
#pragma unroll
        for (int mt = 0; mt < 4; mt++) {
#pragma unroll
            for (int n8 = 0; n8 < 4; n8++) {
                int q2 = n8 >> 1, sub = n8 & 1;
                unsigned bh0 = sub ? bh[q2].z : bh[q2].x;
                unsigned bh1 = sub ? bh[q2].w : bh[q2].y;
                unsigned bl0 = sub ? bl[q2].z : bl[q2].x;
                unsigned bl1 = sub ? bl[q2].w : bl[q2].y;
                MMA_F16(acc[mt][n8][0], acc[mt][n8][1], acc[mt][n8][2], acc[mt][n8][3],
                        ah[mt].x, ah[mt].y, ah[mt].z, ah[mt].w, bh0, bh1);
                MMA_F16(acc[mt][n8][0], acc[mt][n8][1], acc[mt][n8][2], acc[mt][n8][3],
                        ah[mt].x, ah[mt].y, ah[mt].z, ah[mt].w, bl0, bl1);
                MMA_F16(acc[mt][n8][0], acc[mt][n8][1], acc[mt][n8][2], acc[mt][n8][3],
                        al[mt].x, al[mt].y, al[mt].z, al[mt].w, bh0, bh1);
            }
        }
    }

    int mb = blockIdx.y * 128 + wm * 64;
    int nb = blockIdx.x * 128 + wn * 32;
#pragma unroll
    for (int mt = 0; mt < 4; mt++) {
        int r0 = mb + mt * 16 + (lane >> 2);
#pragma unroll
        for (int n8 = 0; n8 < 4; n8++) {
            int n = nb + n8 * 8 + (lane & 3) * 2;
            float b0 = bias[n], b1 = bias[n + 1];
#pragma unroll
            for (int rh = 0; rh < 2; rh++) {
                int m = r0 + rh * 8;
                if (m < Mlim) {
                    size_t base = ((size_t)(m >> 5) * XN + n) * 32 + (m & 15) * 2 + ((m >> 4) & 1);
                    out[base]      = acc[mt][n8][rh * 2 + 0] + b0;
                    out[base + 32] = acc[mt][n8][rh * 2 + 1] + b1;
                }
            }
        }
    }
}

__device__ __forceinline__ void lstm_cell(float ai, float af, float ag, float ao,
                                          float& c, float& h) {
    float si = 1.f / (1.f + expf(-ai));
    float sf = 1.f / (1.f + expf(-af));
    float so = 1.f / (1.f + expf(-ao));
    float tg = tanhf(ag);
    c = sf * c + si * tg;
    h = so * tanhf(c);
}

#define HS_ROW 9

// =====================================================================
// enc scan: 128 blocks x 512 threads. blocks[0,64)=fwd, [64,128)=bwd.
// 8 j/block; 2 warps per j. Full-h single-stage (74KB smem), fence-free
// barrier.
// =====================================================================
__global__ void __launch_bounds__(512) k_enc_scan(const float* __restrict__ Whf,
                                                  const float* __restrict__ Whb) {
    __shared__ float4 hsh4[512 * HS_ROW];   // 73.7 KB: full h, padded rows
    __shared__ ull gsh[8][2][4][8];
    int tid = threadIdx.x, w = tid >> 5, lane = tid & 31;
    int g = lane & 3, kc = lane >> 2;
    int jl = w >> 1, bhalf = w & 1;
    int dir = blockIdx.x >> 6;
    int j = (blockIdx.x & 63) * 8 + jl;
    int pq = lane & 7, chalf = (lane >> 3) & 1;
    int bp = bhalf * 8 + pq;
    bool cell_lane = (lane < 16);

    const float* gx = dir ? d_gxb : d_gxf;
    const float* Whh = dir ? Whb : Whf;
    float* hbuf = d_hping + (size_t)dir * (2 * Hh * Bz);
    ull* lf = d_lf_enc + dir * 64;
    ull* rt = &d_rt_enc2[dir * 16];

    float wreg[64];
    {
        const float* wrow = Whh + ((size_t)g * Hh + j) * Hh + kc;
#pragma unroll
        for (int kk = 0; kk < 64; kk++) wreg[kk] = wrow[kk * 8];
    }
    float c = 0.f, h = 0.f;

    for (int s = 0; s < Ss; s++) {
        float ga0 = 0.f, ga1 = 0.f, ga2 = 0.f, ga3 = 0.f;
        if (cell_lane) {
            const float* gxs = gx + (size_t)s * G4 * Bz;
            ga0 = gxs[(0 * Hh + j) * Bz + bp * 2 + chalf];
            ga1 = gxs[(1 * Hh + j) * Bz + bp * 2 + chalf];
            ga2 = gxs[(2 * Hh + j) * Bz + bp * 2 + chalf];
            ga3 = gxs[(3 * Hh + j) * Bz + bp * 2 + chalf];
        }

        if (s > 0) {
            ull acc[8];
#pragma unroll
            for (int i = 0; i < 8; i++) acc[i] = 0ULL;
            const float4* src = (const float4*)(hbuf + (size_t)(s & 1) * (Hh * Bz));
            // single-stage: full 64KB h, 8-deep MLP
#pragma unroll
            for (int r = 0; r < 8; r++) {
                int ii = tid + r * 512;
                hsh4[(ii >> 3) * HS_ROW + (ii & 7)] = src[ii];
            }
            __syncthreads();
            const ulonglong2* hs2 = (const ulonglong2*)hsh4;
#pragma unroll 16
            for (int kk = 0; kk < 64; kk++) {
                float wv = wreg[kk];
                ull w2 = pack2(wv, wv);
                const ulonglong2* row = hs2 + (kc + (kk << 3)) * HS_ROW + bhalf * 4;
#pragma unroll
                for (int bq = 0; bq < 4; bq++) {
                    ulonglong2 hv = row[bq];
                    acc[2 * bq]     = ffma2(w2, hv.x, acc[2 * bq]);
                    acc[2 * bq + 1] = ffma2(w2, hv.y, acc[2 * bq + 1]);
                }
            }
#pragma unroll
            for (int i = 0; i < 8; i++) {
                acc[i] = fadd2(acc[i], __shfl_xor_sync(0xffffffffu, acc[i], 4));
                acc[i] = fadd2(acc[i], __shfl_xor_sync(0xffffffffu, acc[i], 8));
                acc[i] = fadd2(acc[i], __shfl_xor_sync(0xffffffffu, acc[i], 16));
            }
            if (lane < 4) {
#pragma unroll
                for (int i = 0; i < 8; i++) gsh[jl][bhalf][lane][i] = acc[i];
            }
            __syncwarp();
            if (cell_lane) {
                const float* gsf = (const float*)&gsh[jl][bhalf][0][0];
                ga0 += gsf[(0 * 8 + pq) * 2 + chalf];
                ga1 += gsf[(1 * 8 + pq) * 2 + chalf];
                ga2 += gsf[(2 * 8 + pq) * 2 + chalf];
                ga3 += gsf[(3 * 8 + pq) * 2 + chalf];
            }
            __syncwarp();
        }
        if (cell_lane) {
            lstm_cell(ga0, ga1, ga2, ga3, c, h);
            hbuf[(size_t)((s + 1) & 1) * (Hh * Bz) + (j * 16 + bp) * 2 + chalf] = h;
        }
        grid_sync2(lf, rt, blockIdx.x & 63, 4);
    }
    if (cell_lane) {
        d_hfin[(size_t)dir * (Hh * Bz) + (j * 16 + bp) * 2 + chalf] = h;
        d_cfin[(size_t)dir * (Hh * Bz) + (j * 16 + bp) * 2 + chalf] = c;
    }
}

// =====================================================================
// dec scan: 128 blocks x 512 threads. 4 j/block; 4 warps per j.
// Full-h single-stage, fence-free barrier.
// =====================================================================
__global__ void __launch_bounds__(512) k_dec_scan(const float* __restrict__ Whh) {
    __shared__ float4 hsh4[512 * HS_ROW];
    __shared__ ull gsh[4][4][4][4];
    int tid = threadIdx.x, w = tid >> 5, lane = tid & 31;
    int g = lane & 3, kc = lane >> 2;
    int jl = w >> 2, bq4 = w & 3;
    int j = blockIdx.x * 4 + jl;
    int pq = lane & 3, chalf = (lane >> 2) & 1;
    int bp = bq4 * 4 + pq;
    bool cell_lane = (lane < 8);

    float wreg[64];
    {
        const float* wrow = Whh + ((size_t)g * Hh + j) * Hh + kc;
#pragma unroll
        for (int kk = 0; kk < 64; kk++) wreg[kk] = wrow[kk * 8];
    }
    float c = cell_lane ? d_c0[(j * 16 + bp) * 2 + chalf] : 0.f;
    float h = 0.f;

    int ks_j = j >> 4;
    int khi_j = (j >> 3) & 1;
    int tig_j = (j & 7) >> 1;
    int kpar_j = j & 1;

    for (int t = 0; t < Tt - 1; t++) {
        float ga0 = 0.f, ga1 = 0.f, ga2 = 0.f, ga3 = 0.f;
        if (cell_lane) {
            const float* gxs = d_gxd + (size_t)t * G4 * Bz;
            ga0 = gxs[(0 * Hh + j) * Bz + bp * 2 + chalf];
            ga1 = gxs[(1 * Hh + j) * Bz + bp * 2 + chalf];
            ga2 = gxs[(2 * Hh + j) * Bz + bp * 2 + chalf];
            ga3 = gxs[(3 * Hh + j) * Bz + bp * 2 + chalf];
        }

        ull acc[4];
#pragma unroll
        for (int i = 0; i < 4; i++) acc[i] = 0ULL;
        const float4* src = (const float4*)(d_hdping + (size_t)(t & 1) * (Hh * Bz));
#pragma unroll
        for (int r = 0; r < 8; r++) {
            int ii = tid + r * 512;
            hsh4[(ii >> 3) * HS_ROW + (ii & 7)] = src[ii];
        }
        __syncthreads();
        const ulonglong2* hs2 = (const ulonglong2*)hsh4;
#pragma unroll 16
        for (int kk = 0; kk < 64; kk++) {
            float wv = wreg[kk];
            ull w2 = pack2(wv, wv);
            const ulonglong2* row = hs2 + (kc + (kk << 3)) * HS_ROW + bq4 * 2;
#pragma unroll
            for (int bq = 0; bq < 2; bq++) {
                ulonglong2 hv = row[bq];
                acc[2 * bq]     = ffma2(w2, hv.x, acc[2 * bq]);
                acc[2 * bq + 1] = ffma2(w2, hv.y, acc[2 * bq + 1]);
            }
        }
#pragma unroll
        for (int i = 0; i < 4; i++) {
            acc[i] = fadd2(acc[i], __shfl_xor_sync(0xffffffffu, acc[i], 4));
            acc[i] = fadd2(acc[i], __shfl_xor_sync(0xffffffffu, acc[i], 8));
            acc[i] = fadd2(acc[i], __shfl_xor_sync(0xffffffffu, acc[i], 16));
        }
        if (lane < 4) {
#pragma unroll
            for (int i = 0; i < 4; i++) gsh[jl][bq4][lane][i] = acc[i];
        }
        __syncwarp();
        if (cell_lane) {
            const float* gsf = (const float*)&gsh[jl][bq4][0][0];
            ga0 += gsf[(0 * 4 + pq) * 2 + chalf];
            ga1 += gsf[(1 * 4 + pq) * 2 + chalf];
            ga2 += gsf[(2 * 4 + pq) * 2 + chalf];
            ga3 += gsf[(3 * 4 + pq) * 2 + chalf];
            lstm_cell(ga0, ga1, ga2, ga3, c, h);
            d_hdping[(size_t)((t + 1) & 1) * (Hh * Bz) + (j * 16 + bp) * 2 + chalf] = h;
            int mrow = t * 32 + bp + 16 * chalf;
            int chunk = mrow >> 6;
            int mt = (mrow >> 4) & 3;
            int row16 = mrow & 15;
            int ga = row16 & 7, hi8 = row16 >> 3;
            int lane_f = ga * 4 + tig_j;
            int comp = hi8 + 2 * khi_j;
            size_t hidx = (((size_t)chunk * 4096 + ks_j * 128 + mt * 32 + lane_f) * 4
                           + comp) * 2 + kpar_j;
            ((__half*)d_ahf)[hidx] = __float2half_rn(h);
        }
        grid_sync2(d_lf_dec, &d_rt_dec, blockIdx.x, 8);
    }
}

__global__ void __launch_bounds__(256) k_h0c0(const float* __restrict__ Wh,
                                              const float* __restrict__ bh,
                                              const float* __restrict__ Wc,
                                              const float* __restrict__ bc) {
    int gg = blockIdx.x * blockDim.x + threadIdx.x;
    int j = gg >> 5, b = gg & 31;
    int bp = b & 15, hf = b >> 4;
    const float* hfp = d_hfin + bp * 2 + hf;
    const float* cfp = d_cfin + bp * 2 + hf;
    const float* whr = Wh + (size_t)j * (2 * Hh);
    const float* wcr = Wc + (size_t)j * (2 * Hh);
    float ah = bh[j], ac = bc[j];
#pragma unroll 8
    for (int k = 0; k < 2 * Hh; k++) {
        ah += whr[k] * hfp[k * 32];
        ac += wcr[k] * cfp[k * 32];
    }
    d_hdping[(j * 16 + bp) * 2 + hf] = ah;
    d_c0[(j * 16 + bp) * 2 + hf] = ac;
}

// Logits: fp16 m16n8k16. CTA 128m x 256n, 512 threads, warp 64x32.
__global__ void __launch_bounds__(512, 1) k_logits_h(const float* __restrict__ fcb,
                                                     float* __restrict__ out) {
    int tid = threadIdx.x, w = tid >> 5, lane = tid & 31;
    int wm = w & 1, wn = w >> 1;
    int mtile = blockIdx.y, ntile = blockIdx.x;

    const uint4* Ab = d_ahf + (size_t)(mtile * 2 + wm) * 4096 + lane;
    const uint4* Bb = d_whf + (size_t)(ntile * 4 + (wn >> 1)) * 4096
                      + (wn & 1) * 64 + lane;

    float acc[4][4][4];
#pragma unroll
    for (int a = 0; a < 4; a++)
#pragma unroll
        for (int b = 0; b < 4; b++)
#pragma unroll
            for (int cc = 0; cc < 4; cc++) acc[a][b][cc] = 0.f;

    uint4 av[2][4], bv[2][2];
#pragma unroll
    for (int q = 0; q < 4; q++) av[0][q] = Ab[q * 32];
#pragma unroll
    for (int p = 0; p < 2; p++) bv[0][p] = Bb[p * 32];

    for (int ks = 0; ks < 32; ks++) {
        int cur = ks & 1, nxt = cur ^ 1;
        if (ks < 31) {
            const uint4* An = Ab + (ks + 1) * 128;
            const uint4* Bn = Bb + (ks + 1) * 128;
#pragma unroll
            for (int q = 0; q < 4; q++) av[nxt][q] = An[q * 32];
#pragma unroll
            for (int p = 0; p < 2; p++) bv[nxt][p] = Bn[p * 32];
        }
#pragma unroll
        for (int mt = 0; mt < 4; mt++) {
            unsigned a0 = av[cur][mt].x, a1 = av[cur][mt].y;
            unsigned a2 = av[cur][mt].z, a3 = av[cur][mt].w;
#pragma unroll
            for (int p = 0; p < 2; p++) {
                MMA_F16(acc[mt][2 * p][0], acc[mt][2 * p][1],
                        acc[mt][2 * p][2], acc[mt][2 * p][3],
                        a0, a1, a2, a3, bv[cur][p].x, bv[cur][p].y);
                MMA_F16(acc[mt][2 * p + 1][0], acc[mt][2 * p + 1][1],
                        acc[mt][2 * p + 1][2], acc[mt][2 * p + 1][3],
                        a0, a1, a2, a3, bv[cur][p].z, bv[cur][p].w);
            }
        }
    }

    int mb = mtile * 128 + wm * 64;
    int nb = ntile * 256 + wn * 32;
#pragma unroll
    for (int mt = 0; mt < 4; mt++) {
        int r0 = mb + mt * 16 + (lane >> 2);
#pragma unroll
        for (int nt = 0; nt < 4; nt++) {
            int n = nb + nt * 8 + (lane & 3) * 2;
            if (n >= Vv) continue;
            float b0 = fcb[n];
            float b1 = fcb[n + 1];
#pragma unroll
            for (int rh = 0; rh < 2; rh++) {
                int m = r0 + rh * 8;
                if (m < 3040) {
                    int b = m & 31, ts = m >> 5;
                    size_t o = ((size_t)b * Tt + ts + 1) * (size_t)Vv + n;
                    out[o]     = acc[mt][nt][rh * 2 + 0] + b0;
                    out[o + 1] = acc[mt][nt][rh * 2 + 1] + b1;
                }
            }
        }
    }
}

extern "C" void kernel_launch(void* const* d_in, const int* in_sizes, int n_in,
                              void* d_out, int out_size) {
    (void)in_sizes; (void)n_in; (void)out_size;
    const int*   Problem   = (const int*)d_in[0];
    const int*   LF        = (const int*)d_in[1];
    const float* enc_embed = (const float*)d_in[2];
    const float* dec_embed = (const float*)d_in[3];
    const float* enc_Wih_f = (const float*)d_in[4];
    const float* enc_Whh_f = (const float*)d_in[5];
    const float* enc_b_f   = (const float*)d_in[6];
    const float* enc_Wih_b = (const float*)d_in[7];
    const float* enc_Whh_b = (const float*)d_in[8];
    const float* enc_b_b   = (const float*)d_in[9];
    const float* Wh        = (const float*)d_in[10];
    const float* bh        = (const float*)d_in[11];
    const float* Wc        = (const float*)d_in[12];
    const float* bc        = (const float*)d_in[13];
    const float* dec_Wih   = (const float*)d_in[14];
    const float* dec_Whh   = (const float*)d_in[15];
    const float* dec_b     = (const float*)d_in[16];
    const float* fc_W      = (const float*)d_in[17];
    const float* fc_b      = (const float*)d_in[18];
    float* out = (float*)d_out;

    k_idx<<<(Bz * Vv + 255) / 256, 256>>>(Problem, LF, out);   // 0
    {
        dim3 g(312, 1, 6);
        k_perm_all<<<g, 256>>>(enc_embed, dec_embed, enc_Wih_f, enc_Wih_b, dec_Wih); // 1
    }
    {
        dim3 g(XN / 128, XM / 128, 3);
        k_xg<<<g, 256>>>(enc_b_f, enc_b_b, dec_b);             // 2
    }

    k_enc_scan<<<128, 512>>>(enc_Whh_f, enc_Whh_b);            // 3 <- profiled
    k_h0c0<<<64, 256>>>(Wh, bh, Wc, bc);                       // 4
    k_dec_scan<<<128, 512>>>(dec_Whh);                         // 5
    {
        dim3 g(VPAD / 64, Hh / 64);
        k_permW<<<g, 256>>>(fc_W);                             // 6
    }
    {
        dim3 g(VPAD / 256, MPAD / 128);
        k_logits_h<<<g, 512>>>(fc_b, out);                     // 7
    }
}

// round 17
// speedup vs baseline: 1.0222x; 1.0095x over previous
#include <cuda_runtime.h>
#include <cuda_fp16.h>
#include <math.h>
#include <stdint.h>

#define Bz 32
#define Ss 96
#define Tt 96
#define Ee 200
#define Hh 512
#define Vv 30000
#define G4 2048
#define VPAD 30208   // 118 * 256
#define MPAD 3072    // 24 * 128
#define XM 3072
#define XN 2048
#define XK 200
#define NKS 13       // ceil(200/16)

typedef unsigned long long ull;

// Pair layout for (k,b) arrays: element (k,b) at [(k*16+(b&15))*2 + (b>>4)]
__device__ float d_gxf[(size_t)Ss * G4 * Bz];
__device__ float d_gxb[(size_t)Ss * G4 * Bz];
__device__ float d_gxd[(size_t)(Tt - 1) * G4 * Bz];
__device__ float d_hping[2 * 2 * Hh * Bz];
__device__ float d_hdping[2 * Hh * Bz];
__device__ float d_hfin[2 * Hh * Bz];
__device__ float d_cfin[2 * Hh * Bz];
__device__ float d_c0[Hh * Bz];
// fp16 fragment buffers
__device__ uint4 d_ahf[(size_t)MPAD * Hh / 8];   // decoder h, m16n8k16 A-frag
__device__ uint4 d_whf[(size_t)VPAD * Hh / 8];   // fc_W, m16n8k16 B-frag
// x-gemm fp16 hi/lo fragment buffers
__device__ uint4 d_x16ah[3][48 * 4 * NKS * 32];
__device__ uint4 d_x16al[3][48 * 4 * NKS * 32];
__device__ uint4 d_x16bh[3][64 * NKS * 2 * 32];
__device__ uint4 d_x16bl[3][64 * NKS * 2 * 32];
__device__ int d_idxf[Ss * Bz];
__device__ int d_idxb[Ss * Bz];
__device__ int d_idxd[(Tt - 1) * Bz];
__device__ ull d_lf_enc[8 * 16];
__device__ ull d_rt_enc2[32];
__device__ ull d_lf_dec[8 * 16];
__device__ ull d_rt_dec;

__device__ __forceinline__ ull pack2(float x, float y) {
    ull r; asm("mov.b64 %0,{%1,%2};" : "=l"(r) : "f"(x), "f"(y)); return r;
}
__device__ __forceinline__ ull ffma2(ull a, ull b, ull c) {
    ull d; asm("fma.rn.f32x2 %0,%1,%2,%3;" : "=l"(d) : "l"(a), "l"(b), "l"(c)); return d;
}
__device__ __forceinline__ ull fadd2(ull a, ull b) {
    ull d; asm("add.rn.f32x2 %0,%1,%2;" : "=l"(d) : "l"(a), "l"(b)); return d;
}

// Fence-free grid barrier with bounded-backoff polling.
// Release atomics publish; acquire loads subscribe; after a few fast polls,
// nanosleep backoff collapses the L2 spin storm (contention-tail killer).
__device__ __forceinline__ void grid_sync2(ull* leaf, ull* root, int lbid, int nleaf) {
    __syncthreads();
    if (threadIdx.x == 0) {
        ull a;
        asm volatile("atom.add.release.gpu.u64 %0, [%1], 1;"
                     : "=l"(a) : "l"(leaf + (lbid >> 4) * 16) : "memory");
        a += 1ULL;
        ull phase = (a - 1ULL) >> 4;
        if ((a & 15ULL) == 0ULL)
            asm volatile("red.add.release.gpu.u64 [%0], 1;" :: "l"(root) : "memory");
        ull target = (phase + 1ULL) * (ull)nleaf;
        ull v;
        int spins = 0;
        for (;;) {
            asm volatile("ld.acquire.gpu.u64 %0, [%1];" : "=l"(v) : "l"(root) : "memory");
            if (v >= target) break;
            if (++spins > 4) __nanosleep(64);
        }
    }
    __syncthreads();
}

__device__ __forceinline__ void split_h2(float x0, float x1, unsigned& hi, unsigned& lo) {
    __half h0 = __float2half_rn(x0), h1 = __float2half_rn(x1);
    __half l0 = __float2half_rn(x0 - __half2float(h0));
    __half l1 = __float2half_rn(x1 - __half2float(h1));
    __half2 hh = __halves2half2(h0, h1), ll = __halves2half2(l0, l1);
    hi = *(unsigned*)&hh; lo = *(unsigned*)&ll;
}

// launch 0: indices + d_ahf pad zero + output t=0 zero slice (merged)
__global__ void k_idx(const int* __restrict__ Problem, const int* __restrict__ LF,
                      float* __restrict__ out) {
    long m = (long)blockIdx.x * blockDim.x + threadIdx.x;
    if (m < Ss * Bz) {
        int s = (int)m >> 5, b = (int)m & 31;
        d_idxf[m] = Problem[b * Ss + s];
        d_idxb[m] = Problem[b * Ss + (Ss - 1 - s)];
    }
    if (m < (Tt - 1) * Bz) {
        int t = (int)m >> 5, b = (int)m & 31;
        d_idxd[m] = LF[b * Tt + t];
    }
    if (m < 4096) {
        d_ahf[(size_t)47 * 4096 + m] = make_uint4(0u, 0u, 0u, 0u);
    }
    if (m < (long)Bz * Vv) {
        long b = m / Vv;
        long n = m - b * Vv;
        out[b * (long)Tt * Vv + n] = 0.f;
    }
}

// launch 1: all operand perms for the x-gate GEMMs (z in [0,6))
__global__ void __launch_bounds__(256) k_perm_all(const float* __restrict__ Eenc,
                                                  const float* __restrict__ Edec,
                                                  const float* __restrict__ W0,
                                                  const float* __restrict__ W1,
                                                  const float* __restrict__ W2) {
    int z = blockIdx.z;
    if (z < 3) {
        int which = z;
        int Mlim = (which == 2) ? 3040 : XM;
        const float* E = (which == 2) ? Edec : Eenc;
        const int* ridx = (which == 0) ? d_idxf : (which == 1) ? d_idxb : d_idxd;
        int o = blockIdx.x * 256 + threadIdx.x;
        int lane = o & 31;
        int t = o >> 5;
        int ks = t % NKS;
        int t2 = t / NKS;
        int mt = t2 & 3, wt = t2 >> 2;
        int kb = ks * 16 + (lane & 3) * 2;
        int mrow = wt * 64 + mt * 16 + (lane >> 2);
        unsigned hic[4], loc[4];
#pragma unroll
        for (int c = 0; c < 4; c++) {
            int hi8 = c & 1, khi = c >> 1;
            int m = mrow + hi8 * 8;
            int k = kb + khi * 8;
            float v0 = 0.f, v1 = 0.f;
            if (m < Mlim && k < XK) {
                const float* r = E + (size_t)ridx[m] * XK;
                v0 = r[k];
                if (k + 1 < XK) v1 = r[k + 1];
            }
            split_h2(v0, v1, hic[c], loc[c]);
        }
        d_x16ah[which][o] = make_uint4(hic[0], hic[1], hic[2], hic[3]);
        d_x16al[which][o] = make_uint4(loc[0], loc[1], loc[2], loc[3]);
    } else {
        if (blockIdx.x >= 208) return;
        int which = z - 3;
        const float* W = (which == 0) ? W0 : (which == 1) ? W1 : W2;
        int o = blockIdx.x * 256 + threadIdx.x;
        int lane = o & 31;
        int q2 = (o >> 5) & 1;
        int t = o >> 6;
        int ks = t % NKS;
        int nt = t / NKS;
        unsigned hic[4], loc[4];
#pragma unroll
        for (int c = 0; c < 4; c++) {
            int sub = c >> 1, khi = c & 1;
            int n = nt * 32 + (q2 * 2 + sub) * 8 + (lane >> 2);
            int k = ks * 16 + khi * 8 + (lane & 3) * 2;
            float v0 = 0.f, v1 = 0.f;
            if (k < XK) {
                v0 = W[(size_t)n * XK + k];
                if (k + 1 < XK) v1 = W[(size_t)n * XK + k + 1];
            }
            split_h2(v0, v1, hic[c], loc[c]);
        }
        d_x16bh[which][o] = make_uint4(hic[0], hic[1], hic[2], hic[3]);
        d_x16bl[which][o] = make_uint4(loc[0], loc[1], loc[2], loc[3]);
    }
}

// ---- permW v2: smem-tiled, coalesced. grid (472, 8) -----------------------
__global__ void __launch_bounds__(256) k_permW(const float* __restrict__ W) {
    __shared__ float sw[64][65];
    int tid = threadIdx.x;
    int n0 = blockIdx.x * 64;
    int k0 = blockIdx.y * 64;
    for (int i = tid; i < 1024; i += 256) {
        int row = i >> 4, f4 = i & 15;
        float4 v = make_float4(0.f, 0.f, 0.f, 0.f);
        if (n0 + row < Vv)
            v = *(const float4*)(W + (size_t)(n0 + row) * Hh + k0 + f4 * 4);
        sw[row][f4 * 4 + 0] = v.x; sw[row][f4 * 4 + 1] = v.y;
        sw[row][f4 * 4 + 2] = v.z; sw[row][f4 * 4 + 3] = v.w;
    }
    __syncthreads();
    for (int e = tid; e < 512; e += 256) {
        int lane = e & 31, q = (e >> 5) & 3, ksl = (e >> 7) & 3;
        unsigned comp[4];
#pragma unroll
        for (int c = 0; c < 4; c++) {
            int sub = c >> 1, khi = c & 1;
            int nl = (q * 2 + sub) * 8 + (lane >> 2);
            int kl = ksl * 16 + khi * 8 + (lane & 3) * 2;
            __half2 h2 = __floats2half2_rn(sw[nl][kl], sw[nl][kl + 1]);
            comp[c] = *(unsigned*)&h2;
        }
        int ks_g = blockIdx.y * 4 + ksl;
        d_whf[(size_t)blockIdx.x * 4096 + ks_g * 128 + q * 32 + lane]
            = make_uint4(comp[0], comp[1], comp[2], comp[3]);
    }
}

#define MMA_F16(c0, c1, c2, c3, A0, A1, A2, A3, B0, B1) \
    asm volatile( \
        "mma.sync.aligned.m16n8k16.row.col.f32.f16.f16.f32 " \
        "{%0,%1,%2,%3},{%4,%5,%6,%7},{%8,%9},{%0,%1,%2,%3};" \
        : "+f"(c0), "+f"(c1), "+f"(c2), "+f"(c3) \
        : "r"(A0), "r"(A1), "r"(A2), "r"(A3), "r"(B0), "r"(B1))

// ---- x-gate GEMMs, fp16 hi/lo 3-term ---------------------------------------
__global__ void __launch_bounds__(256) k_xg(const float* __restrict__ bias0,
                                            const float* __restrict__ bias1,
                                            const float* __restrict__ bias2) {
    int which = blockIdx.z;
    const float* bias = (which == 0) ? bias0 : (which == 1) ? bias1 : bias2;
    int Mlim = (which == 2) ? 3040 : XM;
    float* out = (which == 0) ? d_gxf : (which == 1) ? d_gxb : d_gxd;
    int tid = threadIdx.x, w = tid >> 5, lane = tid & 31;
    int wm = w & 1, wn = w >> 1;
    int wt = blockIdx.y * 2 + wm;
    int nt = blockIdx.x * 4 + wn;
    const uint4* Ah = d_x16ah[which] + (size_t)wt * 4 * NKS * 32 + lane;
    const uint4* Al = d_x16al[which] + (size_t)wt * 4 * NKS * 32 + lane;
    const uint4* Bh = d_x16bh[which] + (size_t)nt * NKS * 2 * 32 + lane;
    const uint4* Bl = d_x16bl[which] + (size_t)nt * NKS * 2 * 32 + lane;

    float acc[4][4][4];
#pragma unroll
    for (int a = 0; a < 4; a++)
#pragma unroll
        for (int b = 0; b < 4; b++)
#pragma unroll
            for (int cc = 0; cc < 4; cc++) acc[a][b][cc] = 0.f;

    for (int ks = 0; ks < NKS; ks++) {
        uint4 ah[4], al[4], bh[2], bl[2];
#pragma unroll
        for (int mt = 0; mt < 4; mt++) {
            ah[mt] = Ah[(mt * NKS + ks) * 32];
            al[mt] = Al[(mt * NKS + ks) * 32];
        }
#pragma unroll
        for (int q2 = 0; q2 < 2; q2++) {
            bh[q2] = Bh[(ks * 2 + q2) * 32];
            bl[q2] = Bl[(ks * 2 + q2) * 32];
        }
#pragma unroll
        for (int mt = 0; mt < 4; mt++) {
#pragma unroll
            for (int n8 = 0; n8 < 4; n8++) {
                int q2 = n8 >> 1, sub = n8 & 1;
                unsigned bh0 = sub ? bh[q2].z : bh[q2].x;
                unsigned bh1 = sub ? bh[q2].w : bh[q2].y;
                unsigned bl0 = sub ? bl[q2].z : bl[q2].x;
                unsigned bl1 = sub ? bl[q2].w : bl[q2].y;
                MMA_F16(acc[mt][n8][0], acc[mt][n8][1], acc[mt][n8][2], acc[mt][n8][3],
                        ah[mt].x, ah[mt].y, ah[mt].z, ah[mt].w, bh0, bh1);
                MMA_F16(acc[mt][n8][0], acc[mt][n8][1], acc[mt][n8][2], acc[mt][n8][3],
                        ah[mt].x, ah[mt].y, ah[mt].z, ah[mt].w, bl0, bl1);
                MMA_F16(acc[mt][n8][0], acc[mt][n8][1], acc[mt][n8][2], acc[mt][n8][3],
                        al[mt].x, al[mt].y, al[mt].z, al[mt].w, bh0, bh1);
            }
        }
    }

    int mb = blockIdx.y * 128 + wm * 64;
    int nb = blockIdx.x * 128 + wn * 32;
#pragma unroll
    for (int mt = 0; mt < 4; mt++) {
        int r0 = mb + mt * 16 + (lane >> 2);
#pragma unroll
        for (int n8 = 0; n8 < 4; n8++) {
            int n = nb + n8 * 8 + (lane & 3) * 2;
            float b0 = bias[n], b1 = bias[n + 1];
#pragma unroll
            for (int rh = 0; rh < 2; rh++) {
                int m = r0 + rh * 8;
                if (m < Mlim) {
                    size_t base = ((size_t)(m >> 5) * XN + n) * 32 + (m & 15) * 2 + ((m >> 4) & 1);
                    out[base]      = acc[mt][n8][rh * 2 + 0] + b0;
                    out[base + 32] = acc[mt][n8][rh * 2 + 1] + b1;
                }
            }
        }
    }
}

__device__ __forceinline__ void lstm_cell(float ai, float af, float ag, float ao,
                                          float& c, float& h) {
    float si = 1.f / (1.f + expf(-ai));
    float sf = 1.f / (1.f + expf(-af));
    float so = 1.f / (1.f + expf(-ao));
    float tg = tanhf(ag);
    c = sf * c + si * tg;
    h = so * tanhf(c);
}

#define HS_ROW 9

// =====================================================================
// enc scan: 128 blocks x 512 threads. blocks[0,64)=fwd, [64,128)=bwd.
// 8 j/block; 2 warps per j. Full-h single-stage (74KB smem), fence-free
// backoff barrier.
// =====================================================================
__global__ void __launch_bounds__(512) k_enc_scan(const float* __restrict__ Whf,
                                                  const float* __restrict__ Whb) {
    __shared__ float4 hsh4[512 * HS_ROW];   // 73.7 KB
    __shared__ ull gsh[8][2][4][8];
    int tid = threadIdx.x, w = tid >> 5, lane = tid & 31;
    int g = lane & 3, kc = lane >> 2;
    int jl = w >> 1, bhalf = w & 1;
    int dir = blockIdx.x >> 6;
    int j = (blockIdx.x & 63) * 8 + jl;
    int pq = lane & 7, chalf = (lane >> 3) & 1;
    int bp = bhalf * 8 + pq;
    bool cell_lane = (lane < 16);

    const float* gx = dir ? d_gxb : d_gxf;
    const float* Whh = dir ? Whb : Whf;
    float* hbuf = d_hping + (size_t)dir * (2 * Hh * Bz);
    ull* lf = d_lf_enc + dir * 64;
    ull* rt = &d_rt_enc2[dir * 16];

    float wreg[64];
    {
        const float* wrow = Whh + ((size_t)g * Hh + j) * Hh + kc;
#pragma unroll
        for (int kk = 0; kk < 64; kk++) wreg[kk] = wrow[kk * 8];
    }
    float c = 0.f, h = 0.f;

    for (int s = 0; s < Ss; s++) {
        float ga0 = 0.f, ga1 = 0.f, ga2 = 0.f, ga3 = 0.f;
        if (cell_lane) {
            const float* gxs = gx + (size_t)s * G4 * Bz;
            ga0 = gxs[(0 * Hh + j) * Bz + bp * 2 + chalf];
            ga1 = gxs[(1 * Hh + j) * Bz + bp * 2 + chalf];
            ga2 = gxs[(2 * Hh + j) * Bz + bp * 2 + chalf];
            ga3 = gxs[(3 * Hh + j) * Bz + bp * 2 + chalf];
        }

        if (s > 0) {
            ull acc[8];
#pragma unroll
            for (int i = 0; i < 8; i++) acc[i] = 0ULL;
            const float4* src = (const float4*)(hbuf + (size_t)(s & 1) * (Hh * Bz));
#pragma unroll
            for (int r = 0; r < 8; r++) {
                int ii = tid + r * 512;
                hsh4[(ii >> 3) * HS_ROW + (ii & 7)] = src[ii];
            }
            __syncthreads();
            const ulonglong2* hs2 = (const ulonglong2*)hsh4;
#pragma unroll 16
            for (int kk = 0; kk < 64; kk++) {
                float wv = wreg[kk];
                ull w2 = pack2(wv, wv);
                const ulonglong2* row = hs2 + (kc + (kk << 3)) * HS_ROW + bhalf * 4;
#pragma unroll
                for (int bq = 0; bq < 4; bq++) {
                    ulonglong2 hv = row[bq];
                    acc[2 * bq]     = ffma2(w2, hv.x, acc[2 * bq]);
                    acc[2 * bq + 1] = ffma2(w2, hv.y, acc[2 * bq + 1]);
                }
            }
#pragma unroll
            for (int i = 0; i < 8; i++) {
                acc[i] = fadd2(acc[i], __shfl_xor_sync(0xffffffffu, acc[i], 4));
                acc[i] = fadd2(acc[i], __shfl_xor_sync(0xffffffffu, acc[i], 8));
                acc[i] = fadd2(acc[i], __shfl_xor_sync(0xffffffffu, acc[i], 16));
            }
            if (lane < 4) {
#pragma unroll
                for (int i = 0; i < 8; i++) gsh[jl][bhalf][lane][i] = acc[i];
            }
            __syncwarp();
            if (cell_lane) {
                const float* gsf = (const float*)&gsh[jl][bhalf][0][0];
                ga0 += gsf[(0 * 8 + pq) * 2 + chalf];
                ga1 += gsf[(1 * 8 + pq) * 2 + chalf];
                ga2 += gsf[(2 * 8 + pq) * 2 + chalf];
                ga3 += gsf[(3 * 8 + pq) * 2 + chalf];
            }
            __syncwarp();
        }
        if (cell_lane) {
            lstm_cell(ga0, ga1, ga2, ga3, c, h);
            hbuf[(size_t)((s + 1) & 1) * (Hh * Bz) + (j * 16 + bp) * 2 + chalf] = h;
        }
        grid_sync2(lf, rt, blockIdx.x & 63, 4);
    }
    if (cell_lane) {
        d_hfin[(size_t)dir * (Hh * Bz) + (j * 16 + bp) * 2 + chalf] = h;
        d_cfin[(size_t)dir * (Hh * Bz) + (j * 16 + bp) * 2 + chalf] = c;
    }
}

// =====================================================================
// dec scan: 128 blocks x 512 threads. 4 j/block; 4 warps per j.
// =====================================================================
__global__ void __launch_bounds__(512) k_dec_scan(const float* __restrict__ Whh) {
    __shared__ float4 hsh4[512 * HS_ROW];
    __shared__ ull gsh[4][4][4][4];
    int tid = threadIdx.x, w = tid >> 5, lane = tid & 31;
    int g = lane & 3, kc = lane >> 2;
    int jl = w >> 2, bq4 = w & 3;
    int j = blockIdx.x * 4 + jl;
    int pq = lane & 3, chalf = (lane >> 2) & 1;
    int bp = bq4 * 4 + pq;
    bool cell_lane = (lane < 8);

    float wreg[64];
    {
        const float* wrow = Whh + ((size_t)g * Hh + j) * Hh + kc;
#pragma unroll
        for (int kk = 0; kk < 64; kk++) wreg[kk] = wrow[kk * 8];
    }
    float c = cell_lane ? d_c0[(j * 16 + bp) * 2 + chalf] : 0.f;
    float h = 0.f;

    int ks_j = j >> 4;
    int khi_j = (j >> 3) & 1;
    int tig_j = (j & 7) >> 1;
    int kpar_j = j & 1;

    for (int t = 0; t < Tt - 1; t++) {
        float ga0 = 0.f, ga1 = 0.f, ga2 = 0.f, ga3 = 0.f;
        if (cell_lane) {
            const float* gxs = d_gxd + (size_t)t * G4 * Bz;
            ga0 = gxs[(0 * Hh + j) * Bz + bp * 2 + chalf];
            ga1 = gxs[(1 * Hh + j) * Bz + bp * 2 + chalf];
            ga2 = gxs[(2 * Hh + j) * Bz + bp * 2 + chalf];
            ga3 = gxs[(3 * Hh + j) * Bz + bp * 2 + chalf];
        }

        ull acc[4];
#pragma unroll
        for (int i = 0; i < 4; i++) acc[i] = 0ULL;
        const float4* src = (const float4*)(d_hdping + (size_t)(t & 1) * (Hh * Bz));
#pragma unroll
        for (int r = 0; r < 8; r++) {
            int ii = tid + r * 512;
            hsh4[(ii >> 3) * HS_ROW + (ii & 7)] = src[ii];
        }
        __syncthreads();
        const ulonglong2* hs2 = (const ulonglong2*)hsh4;
#pragma unroll 16
        for (int kk = 0; kk < 64; kk++) {
            float wv = wreg[kk];
            ull w2 = pack2(wv, wv);
            const ulonglong2* row = hs2 + (kc + (kk << 3)) * HS_ROW + bq4 * 2;
#pragma unroll
            for (int bq = 0; bq < 2; bq++) {
                ulonglong2 hv = row[bq];
                acc[2 * bq]     = ffma2(w2, hv.x, acc[2 * bq]);
                acc[2 * bq + 1] = ffma2(w2, hv.y, acc[2 * bq + 1]);
            }
        }
#pragma unroll
        for (int i = 0; i < 4; i++) {
            acc[i] = fadd2(acc[i], __shfl_xor_sync(0xffffffffu, acc[i], 4));
            acc[i] = fadd2(acc[i], __shfl_xor_sync(0xffffffffu, acc[i], 8));
            acc[i] = fadd2(acc[i], __shfl_xor_sync(0xffffffffu, acc[i], 16));
        }
        if (lane < 4) {
#pragma unroll
            for (int i = 0; i < 4; i++) gsh[jl][bq4][lane][i] = acc[i];
        }
        __syncwarp();
        if (cell_lane) {
            const float* gsf = (const float*)&gsh[jl][bq4][0][0];
            ga0 += gsf[(0 * 4 + pq) * 2 + chalf];
            ga1 += gsf[(1 * 4 + pq) * 2 + chalf];
            ga2 += gsf[(2 * 4 + pq) * 2 + chalf];
            ga3 += gsf[(3 * 4 + pq) * 2 + chalf];
            lstm_cell(ga0, ga1, ga2, ga3, c, h);
            d_hdping[(size_t)((t + 1) & 1) * (Hh * Bz) + (j * 16 + bp) * 2 + chalf] = h;
            int mrow = t * 32 + bp + 16 * chalf;
            int chunk = mrow >> 6;
            int mt = (mrow >> 4) & 3;
            int row16 = mrow & 15;
            int ga = row16 & 7, hi8 = row16 >> 3;
            int lane_f = ga * 4 + tig_j;
            int comp = hi8 + 2 * khi_j;
            size_t hidx = (((size_t)chunk * 4096 + ks_j * 128 + mt * 32 + lane_f) * 4
                           + comp) * 2 + kpar_j;
            ((__half*)d_ahf)[hidx] = __float2half_rn(h);
        }
        grid_sync2(d_lf_dec, &d_rt_dec, blockIdx.x, 8);
    }
}

__global__ void __launch_bounds__(256) k_h0c0(const float* __restrict__ Wh,
                                              const float* __restrict__ bh,
                                              const float* __restrict__ Wc,
                                              const float* __restrict__ bc) {
    int gg = blockIdx.x * blockDim.x + threadIdx.x;
    int j = gg >> 5, b = gg & 31;
    int bp = b & 15, hf = b >> 4;
    const float* hfp = d_hfin + bp * 2 + hf;
    const float* cfp = d_cfin + bp * 2 + hf;
    const float* whr = Wh + (size_t)j * (2 * Hh);
    const float* wcr = Wc + (size_t)j * (2 * Hh);
    float ah = bh[j], ac = bc[j];
#pragma unroll 8
    for (int k = 0; k < 2 * Hh; k++) {
        ah += whr[k] * hfp[k * 32];
        ac += wcr[k] * cfp[k * 32];
    }
    d_hdping[(j * 16 + bp) * 2 + hf] = ah;
    d_c0[(j * 16 + bp) * 2 + hf] = ac;
}

// Logits: fp16 m16n8k16. CTA 128m x 256n, 512 threads, warp 64x32.
__global__ void __launch_bounds__(512, 1) k_logits_h(const float* __restrict__ fcb,
                                                     float* __restrict__ out) {
    int tid = threadIdx.x, w = tid >> 5, lane = tid & 31;
    int wm = w & 1, wn = w >> 1;
    int mtile = blockIdx.y, ntile = blockIdx.x;

    const uint4* Ab = d_ahf + (size_t)(mtile * 2 + wm) * 4096 + lane;
    const uint4* Bb = d_whf + (size_t)(ntile * 4 + (wn >> 1)) * 4096
                      + (wn & 1) * 64 + lane;

    float acc[4][4][4];
#pragma unroll
    for (int a = 0; a < 4; a++)
#pragma unroll
        for (int b = 0; b < 4; b++)
#pragma unroll
            for (int cc = 0; cc < 4; cc++) acc[a][b][cc] = 0.f;

    uint4 av[2][4], bv[2][2];
#pragma unroll
    for (int q = 0; q < 4; q++) av[0][q] = Ab[q * 32];
#pragma unroll
    for (int p = 0; p < 2; p++) bv[0][p] = Bb[p * 32];

    for (int ks = 0; ks < 32; ks++) {
        int cur = ks & 1, nxt = cur ^ 1;
        if (ks < 31) {
            const uint4* An = Ab + (ks + 1) * 128;
            const uint4* Bn = Bb + (ks + 1) * 128;
#pragma unroll
            for (int q = 0; q < 4; q++) av[nxt][q] = An[q * 32];
#pragma unroll
            for (int p = 0; p < 2; p++) bv[nxt][p] = Bn[p * 32];
        }
#pragma unroll
        for (int mt = 0; mt < 4; mt++) {
            unsigned a0 = av[cur][mt].x, a1 = av[cur][mt].y;
            unsigned a2 = av[cur][mt].z, a3 = av[cur][mt].w;
#pragma unroll
            for (int p = 0; p < 2; p++) {
                MMA_F16(acc[mt][2 * p][0], acc[mt][2 * p][1],
                        acc[mt][2 * p][2], acc[mt][2 * p][3],
                        a0, a1, a2, a3, bv[cur][p].x, bv[cur][p].y);
                MMA_F16(acc[mt][2 * p + 1][0], acc[mt][2 * p + 1][1],
                        acc[mt][2 * p + 1][2], acc[mt][2 * p + 1][3],
                        a0, a1, a2, a3, bv[cur][p].z, bv[cur][p].w);
            }
        }
    }

    int mb = mtile * 128 + wm * 64;
    int nb = ntile * 256 + wn * 32;
#pragma unroll
    for (int mt = 0; mt < 4; mt++) {
        int r0 = mb + mt * 16 + (lane >> 2);
#pragma unroll
        for (int nt = 0; nt < 4; nt++) {
            int n = nb + nt * 8 + (lane & 3) * 2;
            if (n >= Vv) continue;
            float b0 = fcb[n];
            float b1 = fcb[n + 1];
#pragma unroll
            for (int rh = 0; rh < 2; rh++) {
                int m = r0 + rh * 8;
                if (m < 3040) {
                    int b = m & 31, ts = m >> 5;
                    size_t o = ((size_t)b * Tt + ts + 1) * (size_t)Vv + n;
                    out[o]     = acc[mt][nt][rh * 2 + 0] + b0;
                    out[o + 1] = acc[mt][nt][rh * 2 + 1] + b1;
                }
            }
        }
    }
}

extern "C" void kernel_launch(void* const* d_in, const int* in_sizes, int n_in,
                              void* d_out, int out_size) {
    (void)in_sizes; (void)n_in; (void)out_size;
    const int*   Problem   = (const int*)d_in[0];
    const int*   LF        = (const int*)d_in[1];
    const float* enc_embed = (const float*)d_in[2];
    const float* dec_embed = (const float*)d_in[3];
    const float* enc_Wih_f = (const float*)d_in[4];
    const float* enc_Whh_f = (const float*)d_in[5];
    const float* enc_b_f   = (const float*)d_in[6];
    const float* enc_Wih_b = (const float*)d_in[7];
    const float* enc_Whh_b = (const float*)d_in[8];
    const float* enc_b_b   = (const float*)d_in[9];
    const float* Wh        = (const float*)d_in[10];
    const float* bh        = (const float*)d_in[11];
    const float* Wc        = (const float*)d_in[12];
    const float* bc        = (const float*)d_in[13];
    const float* dec_Wih   = (const float*)d_in[14];
    const float* dec_Whh   = (const float*)d_in[15];
    const float* dec_b     = (const float*)d_in[16];
    const float* fc_W      = (const float*)d_in[17];
    const float* fc_b      = (const float*)d_in[18];
    float* out = (float*)d_out;

    k_idx<<<(Bz * Vv + 255) / 256, 256>>>(Problem, LF, out);   // 0
    {
        dim3 g(312, 1, 6);
        k_perm_all<<<g, 256>>>(enc_embed, dec_embed, enc_Wih_f, enc_Wih_b, dec_Wih); // 1
    }
    {
        dim3 g(XN / 128, XM / 128, 3);
        k_xg<<<g, 256>>>(enc_b_f, enc_b_b, dec_b);             // 2
    }

    k_enc_scan<<<128, 512>>>(enc_Whh_f, enc_Whh_b);            // 3 <- profiled
    k_h0c0<<<64, 256>>>(Wh, bh, Wc, bc);                       // 4
    k_dec_scan<<<128, 512>>>(dec_Whh);                         // 5
    {
        dim3 g(VPAD / 64, Hh / 64);
        k_permW<<<g, 256>>>(fc_W);                             // 6
    }
    {
        dim3 g(VPAD / 256, MPAD / 128);
        k_logits_h<<<g, 512>>>(fc_b, out);                     // 7
    }
}